// round 8
// baseline (speedup 1.0000x reference)
#include <cuda_runtime.h>
#include <cuda_fp16.h>
#include <math.h>
#include <stdint.h>

#define Bsz 4
#define Sq  2048
#define Dm  1024
#define Hn  16
#define HDm 64
#define FFm 2048
#define ROWS (Bsz * Sq)   // 8192
#define S3  (3 * Dm)      // packed QKV row stride

// ---------------- scratch (no allocations allowed) ----------------
__device__ __half g_xn16[ROWS * Dm];
__device__ __half g_qkv16[ROWS * S3];
__device__ __half g_ao16[ROWS * Dm];
__device__ float  g_x1[ROWS * Dm];
__device__ __half g_xm16[ROWS * Dm];
__device__ __half g_h16[ROWS * FFm];
__device__ __half g_wqkv16[S3 * Dm];
__device__ __half g_wu16[Dm * Dm];
__device__ __half g_w116[FFm * Dm];
__device__ __half g_w216[Dm * FFm];

// ---------------- PTX helpers (sm_80-portable only!) ----------------
__device__ __forceinline__ uint32_t smem_u32(const void* p) {
    uint32_t a;
    asm("{ .reg .u64 t; cvta.to.shared.u64 t, %1; cvt.u32.u64 %0, t; }"
        : "=r"(a) : "l"(p));
    return a;
}
__device__ __forceinline__ void cp16(uint32_t saddr, const void* gaddr) {
    asm volatile("cp.async.cg.shared.global [%0], [%1], 16;"
                 :: "r"(saddr), "l"(gaddr));
}
#define CP_COMMIT() asm volatile("cp.async.commit_group;" ::: "memory")
#define CP_WAIT1()  asm volatile("cp.async.wait_group 1;" ::: "memory")
#define CP_WAIT0()  asm volatile("cp.async.wait_group 0;" ::: "memory")
#define SWZ(o) ((o) ^ (((o) >> 3) & 0x70))

__device__ __forceinline__ void ldsm4(uint32_t* r, uint32_t addr) {
    asm volatile("ldmatrix.sync.aligned.m8n8.x4.shared.b16 {%0,%1,%2,%3}, [%4];"
                 : "=r"(r[0]), "=r"(r[1]), "=r"(r[2]), "=r"(r[3]) : "r"(addr));
}
__device__ __forceinline__ void ldsm4t(uint32_t* r, uint32_t addr) {
    asm volatile("ldmatrix.sync.aligned.m8n8.x4.trans.shared.b16 {%0,%1,%2,%3}, [%4];"
                 : "=r"(r[0]), "=r"(r[1]), "=r"(r[2]), "=r"(r[3]) : "r"(addr));
}
__device__ __forceinline__ void mma16816(float* c, const uint32_t* a,
                                         const uint32_t* b) {
    asm volatile("mma.sync.aligned.m16n8k16.row.col.f32.f16.f16.f32 "
                 "{%0,%1,%2,%3}, {%4,%5,%6,%7}, {%8,%9}, {%0,%1,%2,%3};"
                 : "+f"(c[0]), "+f"(c[1]), "+f"(c[2]), "+f"(c[3])
                 : "r"(a[0]), "r"(a[1]), "r"(a[2]), "r"(a[3]),
                   "r"(b[0]), "r"(b[1]));
}

// fast 2^y on FMA/ALU pipes (y <= 0 expected; clamped). rel err ~1e-6.
#define L2E 1.4426950408889634f
__device__ __forceinline__ float fexp2n(float y) {
    y = fmaxf(y, -125.f);
    float t = y + 12582912.f;               // 1.5 * 2^23 rounding trick
    int n = __float_as_int(t) - 0x4B400000;
    float f = y - (t - 12582912.f);         // f in [-0.5, 0.5]
    float p = 1.f + f * (0.693147182f + f * (0.240226507f + f * (0.0555041087f
              + f * (0.00961812911f + f * 0.00133335581f))));
    return __int_as_float(__float_as_int(p) + (n << 23));
}

// ---------------- fused fp32 -> fp16 weight conversion ----------------
// segments (float4 units): Wq 256K | Wk 256K | Wv 256K | Wu 256K | W1 512K | W2 512K
__global__ void __launch_bounds__(256) f2h_all(
    const float* __restrict__ Wq, const float* __restrict__ Wk,
    const float* __restrict__ Wv, const float* __restrict__ Wu,
    const float* __restrict__ W1, const float* __restrict__ W2)
{
    int v4 = blockIdx.x * 256 + threadIdx.x;   // 0 .. 2M-1
    const float* src;
    __half* dst;
    int base;
    if      (v4 <  262144) { src = Wq; dst = g_wqkv16;               base = 0; }
    else if (v4 <  524288) { src = Wk; dst = g_wqkv16 + 1048576;     base = 262144; }
    else if (v4 <  786432) { src = Wv; dst = g_wqkv16 + 2097152;     base = 524288; }
    else if (v4 < 1048576) { src = Wu; dst = g_wu16;                 base = 786432; }
    else if (v4 < 1572864) { src = W1; dst = g_w116;                 base = 1048576; }
    else                   { src = W2; dst = g_w216;                 base = 1572864; }
    int i = (v4 - base) * 4;
    float4 v = *(const float4*)&src[i];
    *(__half2*)&dst[i]     = __floats2half2_rn(v.x, v.y);
    *(__half2*)&dst[i + 2] = __floats2half2_rn(v.z, v.w);
}

// ---------------- LayerNorm (fp32 in, fp16 out) ----------------
__global__ void __launch_bounds__(256) ln_kernel(const float* __restrict__ x,
                                                 const float* __restrict__ g,
                                                 const float* __restrict__ b,
                                                 __half* __restrict__ out) {
    int row = blockIdx.x;
    const float* xr = x + (size_t)row * Dm;
    int c = threadIdx.x * 4;
    float4 xv = *(const float4*)&xr[c];
    float s  = xv.x + xv.y + xv.z + xv.w;
    float ss = xv.x*xv.x + xv.y*xv.y + xv.z*xv.z + xv.w*xv.w;
    #pragma unroll
    for (int m = 16; m > 0; m >>= 1) {
        s  += __shfl_xor_sync(0xffffffffu, s,  m);
        ss += __shfl_xor_sync(0xffffffffu, ss, m);
    }
    __shared__ float sred[16];
    int w = threadIdx.x >> 5, lane = threadIdx.x & 31;
    if (lane == 0) { sred[w] = s; sred[w + 8] = ss; }
    __syncthreads();
    float tot = 0.f, tot2 = 0.f;
    #pragma unroll
    for (int i = 0; i < 8; i++) { tot += sred[i]; tot2 += sred[8 + i]; }
    float mean = tot * (1.0f / Dm);
    float var  = tot2 * (1.0f / Dm) - mean * mean;
    float rstd = rsqrtf(var + 1e-5f);
    float4 gv = *(const float4*)&g[c];
    float4 bv = *(const float4*)&b[c];
    float o0 = (xv.x - mean) * rstd * gv.x + bv.x;
    float o1 = (xv.y - mean) * rstd * gv.y + bv.y;
    float o2 = (xv.z - mean) * rstd * gv.z + bv.z;
    float o3 = (xv.w - mean) * rstd * gv.w + bv.w;
    __half* orow = out + (size_t)row * Dm + c;
    *(__half2*)&orow[0] = __floats2half2_rn(o0, o1);
    *(__half2*)&orow[2] = __floats2half2_rn(o2, o3);
}

// ---------------- HMMA fp16 GEMM: C[M,N] = A[M,K] @ W[N,K]^T ----------------
#define NST 3
#define STAGE_BYTES 32768
#define GSMEM (1024 + NST * STAGE_BYTES)

__device__ __forceinline__ float gelu_exact(float v) {
    return 0.5f * v * (1.0f + erff(v * 0.70710678118654752f));
}

template<int MODE, typename TOUT>
__global__ void __launch_bounds__(256, 2)
hgemm_mma(const __half* __restrict__ A, const __half* __restrict__ W,
          const float* __restrict__ bias, const float* __restrict__ resid,
          TOUT* __restrict__ C, int M, int N, int K)
{
    extern __shared__ char dsm[];
    uint32_t stage0 = (smem_u32(dsm) + 1023) & ~1023u;

    int tid  = threadIdx.x;
    int wid  = tid >> 5, lane = tid & 31;
    int wm   = wid & 1;
    int wn   = wid >> 1;
    int rowBase = blockIdx.y * 128;
    int colBase = blockIdx.x * 128;
    int nchunk = K >> 6;

    float acc[4][4][4];
    #pragma unroll
    for (int i = 0; i < 4; i++)
        #pragma unroll
        for (int j = 0; j < 4; j++)
            #pragma unroll
            for (int e = 0; e < 4; e++) acc[i][j][e] = 0.f;

    auto fill = [&](int chunk, int stage) {
        uint32_t sA = stage0 + stage * STAGE_BYTES;
        uint32_t sB = sA + 16384;
        const __half* Ab = A + (size_t)rowBase * K + chunk * 64;
        const __half* Wb = W + (size_t)colBase * K + chunk * 64;
        #pragma unroll
        for (int it = 0; it < 8; it++) {
            int idx = it * 256 + tid;
            int half = idx >> 10;
            int sub  = idx & 1023;
            int r = sub >> 3, c = sub & 7;
            uint32_t off = SWZ(r * 128 + c * 16);
            if (half == 0) cp16(sA + off, Ab + (size_t)r * K + c * 8);
            else           cp16(sB + off, Wb + (size_t)r * K + c * 8);
        }
        CP_COMMIT();
    };

    fill(0, 0);
    fill(1, 1);

    int a_row_off = lane & 15;
    int a_k_off   = (lane >> 4) << 4;
    int b_row_off = (lane & 7) + ((lane >> 4) << 3);
    int b_k_off   = ((lane >> 3) & 1) << 4;

    for (int i = 0; i < nchunk; i++) {
        CP_WAIT1();
        __syncthreads();        // orders cp.async visibility AND stage reuse:
                                // fill(i+2) below writes stage (i-1)%3, whose
                                // readers all passed this barrier.
        if (i + 2 < nchunk) fill(i + 2, (i + 2) % NST);

        uint32_t sA = stage0 + (i % NST) * STAGE_BYTES;
        uint32_t sB = sA + 16384;
        #pragma unroll
        for (int ks = 0; ks < 4; ks++) {
            int kb = ks * 32;
            uint32_t af[4][4], bf[2][4];
            #pragma unroll
            for (int m = 0; m < 4; m++) {
                int row = wm * 64 + m * 16 + a_row_off;
                ldsm4(af[m], sA + SWZ(row * 128 + kb + a_k_off));
            }
            #pragma unroll
            for (int j = 0; j < 2; j++) {
                int row = wn * 32 + j * 16 + b_row_off;
                ldsm4(bf[j], sB + SWZ(row * 128 + kb + b_k_off));
            }
            #pragma unroll
            for (int m = 0; m < 4; m++)
                #pragma unroll
                for (int n = 0; n < 4; n++)
                    mma16816(acc[m][n], af[m], &bf[n >> 1][(n & 1) * 2]);
        }
    }

    int r0 = rowBase + wm * 64 + (lane >> 2);
    int c0 = colBase + wn * 32 + (lane & 3) * 2;
    #pragma unroll
    for (int m = 0; m < 4; m++) {
        #pragma unroll
        for (int n = 0; n < 4; n++) {
            int col = c0 + n * 8;
            float2 bi = make_float2(0.f, 0.f);
            if (MODE >= 1) bi = *(const float2*)&bias[col];
            #pragma unroll
            for (int hrow = 0; hrow < 2; hrow++) {
                int row = r0 + m * 16 + hrow * 8;
                float v0 = acc[m][n][hrow * 2 + 0];
                float v1 = acc[m][n][hrow * 2 + 1];
                if (MODE >= 1) { v0 += bi.x; v1 += bi.y; }
                if (MODE == 1) {
                    float2 rr = *(const float2*)&resid[(size_t)row * N + col];
                    v0 += rr.x; v1 += rr.y;
                }
                if (MODE == 2) { v0 = gelu_exact(v0); v1 = gelu_exact(v1); }
                if (sizeof(TOUT) == 2) {
                    *(__half2*)((__half*)C + (size_t)row * N + col) =
                        __floats2half2_rn(v0, v1);
                } else {
                    *(float2*)((float*)C + (size_t)row * N + col) =
                        make_float2(v0, v1);
                }
            }
        }
    }
}

// ---------------- HMMA flash attention (packed QKV input, stride S3) ------
// CTA: 128 threads (4 warps), 64 q-rows. K/V streamed in 64-row tiles,
// double-buffered. smem: Q 8KB | 2 x (K 8KB + V 8KB) | mask 8KB = 48KB.
#define ATTN_SMEM (8192 + 2 * 16384 + 8192)

__global__ void __launch_bounds__(128) attn_mma(
    const __half* __restrict__ qkv, const float* __restrict__ pm,
    __half* __restrict__ out)
{
    extern __shared__ char smraw[];
    uint32_t base = smem_u32(smraw);
    float* Msk = (float*)(smraw + 8192 + 32768);

    int tid = threadIdx.x, wid = tid >> 5, lane = tid & 31;
    int qtile = blockIdx.x, bh = blockIdx.y;
    int b = bh >> 4, h = bh & 15;
    int q0 = qtile * 64;

    const __half* qb = qkv + ((size_t)b * Sq) * S3 + h * HDm;
    const __half* kb = qb + Dm;
    const __half* vb = qb + 2 * Dm;

    // mask -> smem (pre-transformed additive bias)
    {
        const float4* pmb = (const float4*)(pm + (size_t)b * Sq);
        for (int i = tid; i < Sq / 4; i += 128) {
            float4 mv = pmb[i];
            float4 w;
            w.x = (1.f - mv.x) * -10000.f; w.y = (1.f - mv.y) * -10000.f;
            w.z = (1.f - mv.z) * -10000.f; w.w = (1.f - mv.w) * -10000.f;
            ((float4*)Msk)[i] = w;
        }
    }

    // Q tile -> smem (group 0)
    #pragma unroll
    for (int it = 0; it < 4; it++) {
        int idx = it * 128 + tid;
        int r = idx >> 3, c = idx & 7;
        cp16(base + SWZ(r * 128 + c * 16), qb + (size_t)(q0 + r) * S3 + c * 8);
    }
    CP_COMMIT();

    auto fillkv = [&](int kt, int st) {
        uint32_t sK = base + 8192 + st * 16384;
        uint32_t sV = sK + 8192;
        int k0 = kt * 64;
        #pragma unroll
        for (int it = 0; it < 8; it++) {
            int idx = it * 128 + tid;
            int hf = idx >> 9, sub = idx & 511;
            int r = sub >> 3, c = sub & 7;
            uint32_t off = SWZ(r * 128 + c * 16);
            if (hf == 0) cp16(sK + off, kb + (size_t)(k0 + r) * S3 + c * 8);
            else         cp16(sV + off, vb + (size_t)(k0 + r) * S3 + c * 8);
        }
        CP_COMMIT();
    };
    fillkv(0, 0);

    CP_WAIT1();                 // Q tile resident (kv0 may still be in flight)
    __syncthreads();

    int a_row = lane & 15, a_kb = (lane >> 4) << 4;
    int b_row = (lane & 7) + ((lane >> 4) << 3);
    int b_kb  = ((lane >> 3) & 1) << 4;
    int colb  = (lane & 3) * 2;

    uint32_t qf[4][4];
    #pragma unroll
    for (int ks = 0; ks < 4; ks++)
        ldsm4(qf[ks], base + SWZ((wid * 16 + a_row) * 128 + ks * 32 + a_kb));

    float m_[2] = {-1e30f, -1e30f}, l_[2] = {0.f, 0.f};
    float o[8][4];
    #pragma unroll
    for (int nb = 0; nb < 8; nb++)
        #pragma unroll
        for (int e = 0; e < 4; e++) o[nb][e] = 0.f;

    for (int kt = 0; kt < Sq / 64; kt++) {
        int st = kt & 1;
        if (kt + 1 < Sq / 64) { fillkv(kt + 1, st ^ 1); CP_WAIT1(); }
        else                  { CP_WAIT0(); }
        __syncthreads();
        uint32_t sK = base + 8192 + st * 16384;
        uint32_t sV = sK + 8192;
        int k0 = kt * 64;

        // S = Q @ K^T
        float sc[8][4];
        #pragma unroll
        for (int nb = 0; nb < 8; nb++)
            #pragma unroll
            for (int e = 0; e < 4; e++) sc[nb][e] = 0.f;
        #pragma unroll
        for (int np = 0; np < 4; np++) {
            #pragma unroll
            for (int ks = 0; ks < 4; ks++) {
                uint32_t bf[4];
                ldsm4(bf, sK + SWZ((np * 16 + b_row) * 128 + ks * 32 + b_kb));
                mma16816(sc[2 * np],     qf[ks], &bf[0]);
                mma16816(sc[2 * np + 1], qf[ks], &bf[2]);
            }
        }

        // scale + mask + online softmax (fast exp on FMA pipe)
        float ml0 = -1e30f, ml1 = -1e30f;
        #pragma unroll
        for (int nb = 0; nb < 8; nb++) {
            float mk0 = Msk[k0 + nb * 8 + colb];
            float mk1 = Msk[k0 + nb * 8 + colb + 1];
            sc[nb][0] = fmaf(sc[nb][0], 0.125f, mk0);
            sc[nb][1] = fmaf(sc[nb][1], 0.125f, mk1);
            sc[nb][2] = fmaf(sc[nb][2], 0.125f, mk0);
            sc[nb][3] = fmaf(sc[nb][3], 0.125f, mk1);
            ml0 = fmaxf(ml0, fmaxf(sc[nb][0], sc[nb][1]));
            ml1 = fmaxf(ml1, fmaxf(sc[nb][2], sc[nb][3]));
        }
        ml0 = fmaxf(ml0, __shfl_xor_sync(0xffffffffu, ml0, 1));
        ml0 = fmaxf(ml0, __shfl_xor_sync(0xffffffffu, ml0, 2));
        ml1 = fmaxf(ml1, __shfl_xor_sync(0xffffffffu, ml1, 1));
        ml1 = fmaxf(ml1, __shfl_xor_sync(0xffffffffu, ml1, 2));
        float mn0 = fmaxf(m_[0], ml0), mn1 = fmaxf(m_[1], ml1);
        float al0 = fexp2n((m_[0] - mn0) * L2E);
        float al1 = fexp2n((m_[1] - mn1) * L2E);
        float bb0 = mn0 * L2E, bb1 = mn1 * L2E;
        float s0 = 0.f, s1 = 0.f;
        #pragma unroll
        for (int nb = 0; nb < 8; nb++) {
            sc[nb][0] = fexp2n(fmaf(sc[nb][0], L2E, -bb0));
            sc[nb][1] = fexp2n(fmaf(sc[nb][1], L2E, -bb0));
            sc[nb][2] = fexp2n(fmaf(sc[nb][2], L2E, -bb1));
            sc[nb][3] = fexp2n(fmaf(sc[nb][3], L2E, -bb1));
            s0 += sc[nb][0] + sc[nb][1];
            s1 += sc[nb][2] + sc[nb][3];
        }
        s0 += __shfl_xor_sync(0xffffffffu, s0, 1);
        s0 += __shfl_xor_sync(0xffffffffu, s0, 2);
        s1 += __shfl_xor_sync(0xffffffffu, s1, 1);
        s1 += __shfl_xor_sync(0xffffffffu, s1, 2);
        l_[0] = l_[0] * al0 + s0; l_[1] = l_[1] * al1 + s1;
        m_[0] = mn0; m_[1] = mn1;
        #pragma unroll
        for (int nb = 0; nb < 8; nb++) {
            o[nb][0] *= al0; o[nb][1] *= al0;
            o[nb][2] *= al1; o[nb][3] *= al1;
        }

        // O += P @ V  (P stays in registers: S-accum layout == A-frag layout)
        #pragma unroll
        for (int ks = 0; ks < 4; ks++) {
            uint32_t pa[4];
            __half2 p0 = __floats2half2_rn(sc[2*ks][0],   sc[2*ks][1]);
            __half2 p1 = __floats2half2_rn(sc[2*ks][2],   sc[2*ks][3]);
            __half2 p2 = __floats2half2_rn(sc[2*ks+1][0], sc[2*ks+1][1]);
            __half2 p3 = __floats2half2_rn(sc[2*ks+1][2], sc[2*ks+1][3]);
            pa[0] = *(uint32_t*)&p0; pa[1] = *(uint32_t*)&p1;
            pa[2] = *(uint32_t*)&p2; pa[3] = *(uint32_t*)&p3;
            #pragma unroll
            for (int np = 0; np < 4; np++) {
                uint32_t vf[4];
                ldsm4t(vf, sV + SWZ((ks * 16 + a_row) * 128 + np * 32 + a_kb));
                mma16816(o[2 * np],     pa, &vf[0]);
                mma16816(o[2 * np + 1], pa, &vf[2]);
            }
        }
        __syncthreads();
    }

    float inv0 = 1.f / l_[0], inv1 = 1.f / l_[1];
    int r0g = q0 + wid * 16 + (lane >> 2);
    __half* ob = out + ((size_t)b * Sq) * Dm + h * HDm;
    #pragma unroll
    for (int nb = 0; nb < 8; nb++) {
        int col = nb * 8 + colb;
        *(__half2*)&ob[(size_t)r0g * Dm + col] =
            __floats2half2_rn(o[nb][0] * inv0, o[nb][1] * inv0);
        *(__half2*)&ob[(size_t)(r0g + 8) * Dm + col] =
            __floats2half2_rn(o[nb][2] * inv1, o[nb][3] * inv1);
    }
}

// ---------------- launch ----------------
extern "C" void kernel_launch(void* const* d_in, const int* in_sizes, int n_in,
                              void* d_out, int out_size) {
    const float* x     = (const float*)d_in[0];
    const float* pmask = (const float*)d_in[1];
    const float* Wq    = (const float*)d_in[2];
    const float* Wk    = (const float*)d_in[3];
    const float* Wv    = (const float*)d_in[4];
    const float* Wu    = (const float*)d_in[5];
    const float* bu    = (const float*)d_in[6];
    const float* W1    = (const float*)d_in[7];
    const float* b1    = (const float*)d_in[8];
    const float* W2    = (const float*)d_in[9];
    const float* b2    = (const float*)d_in[10];
    const float* g1    = (const float*)d_in[11];
    const float* be1   = (const float*)d_in[12];
    const float* g2    = (const float*)d_in[13];
    const float* be2   = (const float*)d_in[14];
    float* out = (float*)d_out;

    __half *xn16, *qkv16, *ao16, *xm16, *h16;
    __half *wqkv16, *wu16, *w116, *w216;
    float *x1;
    cudaGetSymbolAddress((void**)&xn16,   g_xn16);
    cudaGetSymbolAddress((void**)&qkv16,  g_qkv16);
    cudaGetSymbolAddress((void**)&ao16,   g_ao16);
    cudaGetSymbolAddress((void**)&x1,     g_x1);
    cudaGetSymbolAddress((void**)&xm16,   g_xm16);
    cudaGetSymbolAddress((void**)&h16,    g_h16);
    cudaGetSymbolAddress((void**)&wqkv16, g_wqkv16);
    cudaGetSymbolAddress((void**)&wu16,   g_wu16);
    cudaGetSymbolAddress((void**)&w116,   g_w116);
    cudaGetSymbolAddress((void**)&w216,   g_w216);

    cudaFuncSetAttribute(attn_mma, cudaFuncAttributeMaxDynamicSharedMemorySize,
                         ATTN_SMEM);
    cudaFuncSetAttribute(hgemm_mma<0, __half>,
                         cudaFuncAttributeMaxDynamicSharedMemorySize, GSMEM);
    cudaFuncSetAttribute(hgemm_mma<1, float>,
                         cudaFuncAttributeMaxDynamicSharedMemorySize, GSMEM);
    cudaFuncSetAttribute(hgemm_mma<2, __half>,
                         cudaFuncAttributeMaxDynamicSharedMemorySize, GSMEM);

    // fused weight conversion (8M elements, one launch)
    f2h_all<<<8192, 256>>>(Wq, Wk, Wv, Wu, W1, W2);

    dim3 gQKV(S3 / 128, ROWS / 128);  // (24, 64) -> 1536 CTAs
    dim3 gD(Dm / 128, ROWS / 128);    // (8, 64)
    dim3 gF(FFm / 128, ROWS / 128);   // (16, 64)

    ln_kernel<<<ROWS, 256>>>(x, g1, be1, xn16);

    hgemm_mma<0, __half><<<gQKV, 256, GSMEM>>>(xn16, wqkv16, nullptr, nullptr,
                                               qkv16, ROWS, S3, Dm);

    attn_mma<<<dim3(Sq / 64, Bsz * Hn), 128, ATTN_SMEM>>>(qkv16, pmask, ao16);

    hgemm_mma<1, float><<<gD, 256, GSMEM>>>(ao16, wu16, bu, x, x1, ROWS, Dm, Dm);

    ln_kernel<<<ROWS, 256>>>(x1, g2, be2, xm16);

    hgemm_mma<2, __half><<<gF, 256, GSMEM>>>(xm16, w116, b1, nullptr, h16, ROWS, FFm, Dm);

    hgemm_mma<1, float><<<gD, 256, GSMEM>>>(h16, w216, b2, x1, out, ROWS, Dm, FFm);
}

// round 11
// speedup vs baseline: 1.5083x; 1.5083x over previous
#include <cuda_runtime.h>
#include <cuda_fp16.h>
#include <math.h>
#include <stdint.h>

#define Bsz 4
#define Sq  2048
#define Dm  1024
#define Hn  16
#define HDm 64
#define FFm 2048
#define ROWS (Bsz * Sq)   // 8192

// ---------------- scratch (no allocations allowed) ----------------
__device__ __half g_xn16[ROWS * Dm];
__device__ __half g_q16[ROWS * Dm];
__device__ __half g_k16[ROWS * Dm];
__device__ __half g_v16[ROWS * Dm];
__device__ __half g_ao16[ROWS * Dm];
__device__ float  g_x1[ROWS * Dm];
__device__ __half g_xm16[ROWS * Dm];
__device__ __half g_h16[ROWS * FFm];
__device__ __half g_wqkv16[3 * Dm * Dm];   // Wq | Wk | Wv segments
__device__ __half g_wu16[Dm * Dm];
__device__ __half g_w116[FFm * Dm];
__device__ __half g_w216[Dm * FFm];

// ---------------- PTX helpers (sm_80-portable only!) ----------------
__device__ __forceinline__ uint32_t smem_u32(const void* p) {
    uint32_t a;
    asm("{ .reg .u64 t; cvta.to.shared.u64 t, %1; cvt.u32.u64 %0, t; }"
        : "=r"(a) : "l"(p));
    return a;
}
__device__ __forceinline__ void cp16(uint32_t saddr, const void* gaddr) {
    asm volatile("cp.async.cg.shared.global [%0], [%1], 16;"
                 :: "r"(saddr), "l"(gaddr));
}
#define CP_COMMIT() asm volatile("cp.async.commit_group;" ::: "memory")
#define CP_WAIT1()  asm volatile("cp.async.wait_group 1;" ::: "memory")
#define CP_WAIT0()  asm volatile("cp.async.wait_group 0;" ::: "memory")
#define SWZ(o) ((o) ^ (((o) >> 3) & 0x70))

__device__ __forceinline__ void ldsm4(uint32_t* r, uint32_t addr) {
    asm volatile("ldmatrix.sync.aligned.m8n8.x4.shared.b16 {%0,%1,%2,%3}, [%4];"
                 : "=r"(r[0]), "=r"(r[1]), "=r"(r[2]), "=r"(r[3]) : "r"(addr));
}
__device__ __forceinline__ void ldsm4t(uint32_t* r, uint32_t addr) {
    asm volatile("ldmatrix.sync.aligned.m8n8.x4.trans.shared.b16 {%0,%1,%2,%3}, [%4];"
                 : "=r"(r[0]), "=r"(r[1]), "=r"(r[2]), "=r"(r[3]) : "r"(addr));
}
__device__ __forceinline__ void mma16816(float* c, const uint32_t* a,
                                         const uint32_t* b) {
    asm volatile("mma.sync.aligned.m16n8k16.row.col.f32.f16.f16.f32 "
                 "{%0,%1,%2,%3}, {%4,%5,%6,%7}, {%8,%9}, {%0,%1,%2,%3};"
                 : "+f"(c[0]), "+f"(c[1]), "+f"(c[2]), "+f"(c[3])
                 : "r"(a[0]), "r"(a[1]), "r"(a[2]), "r"(a[3]),
                   "r"(b[0]), "r"(b[1]));
}

// fast 2^y on FMA/ALU pipes (y <= 0 expected; clamped). rel err ~1e-6.
#define L2E 1.4426950408889634f
__device__ __forceinline__ float fexp2n(float y) {
    y = fmaxf(y, -125.f);
    float t = y + 12582912.f;               // 1.5 * 2^23 rounding trick
    int n = __float_as_int(t) - 0x4B400000;
    float f = y - (t - 12582912.f);         // f in [-0.5, 0.5]
    float p = 1.f + f * (0.693147182f + f * (0.240226507f + f * (0.0555041087f
              + f * (0.00961812911f + f * 0.00133335581f))));
    return __int_as_float(__float_as_int(p) + (n << 23));
}

// ---------------- fused fp32 -> fp16 weight conversion ----------------
// segments (float4 units): Wq 256K | Wk 256K | Wv 256K | Wu 256K | W1 512K | W2 512K
__global__ void __launch_bounds__(256) f2h_all(
    const float* __restrict__ Wq, const float* __restrict__ Wk,
    const float* __restrict__ Wv, const float* __restrict__ Wu,
    const float* __restrict__ W1, const float* __restrict__ W2)
{
    int v4 = blockIdx.x * 256 + threadIdx.x;   // 0 .. 2M-1
    const float* src;
    __half* dst;
    int base;
    if      (v4 <  262144) { src = Wq; dst = g_wqkv16;               base = 0; }
    else if (v4 <  524288) { src = Wk; dst = g_wqkv16 + 1048576;     base = 262144; }
    else if (v4 <  786432) { src = Wv; dst = g_wqkv16 + 2097152;     base = 524288; }
    else if (v4 < 1048576) { src = Wu; dst = g_wu16;                 base = 786432; }
    else if (v4 < 1572864) { src = W1; dst = g_w116;                 base = 1048576; }
    else                   { src = W2; dst = g_w216;                 base = 1572864; }
    int i = (v4 - base) * 4;
    float4 v = *(const float4*)&src[i];
    *(__half2*)&dst[i]     = __floats2half2_rn(v.x, v.y);
    *(__half2*)&dst[i + 2] = __floats2half2_rn(v.z, v.w);
}

// ---------------- LayerNorm (fp32 in, fp16 out) ----------------
__global__ void __launch_bounds__(256) ln_kernel(const float* __restrict__ x,
                                                 const float* __restrict__ g,
                                                 const float* __restrict__ b,
                                                 __half* __restrict__ out) {
    int row = blockIdx.x;
    const float* xr = x + (size_t)row * Dm;
    int c = threadIdx.x * 4;
    float4 xv = *(const float4*)&xr[c];
    float s  = xv.x + xv.y + xv.z + xv.w;
    float ss = xv.x*xv.x + xv.y*xv.y + xv.z*xv.z + xv.w*xv.w;
    #pragma unroll
    for (int m = 16; m > 0; m >>= 1) {
        s  += __shfl_xor_sync(0xffffffffu, s,  m);
        ss += __shfl_xor_sync(0xffffffffu, ss, m);
    }
    __shared__ float sred[16];
    int w = threadIdx.x >> 5, lane = threadIdx.x & 31;
    if (lane == 0) { sred[w] = s; sred[w + 8] = ss; }
    __syncthreads();
    float tot = 0.f, tot2 = 0.f;
    #pragma unroll
    for (int i = 0; i < 8; i++) { tot += sred[i]; tot2 += sred[8 + i]; }
    float mean = tot * (1.0f / Dm);
    float var  = tot2 * (1.0f / Dm) - mean * mean;
    float rstd = rsqrtf(var + 1e-5f);
    float4 gv = *(const float4*)&g[c];
    float4 bv = *(const float4*)&b[c];
    float o0 = (xv.x - mean) * rstd * gv.x + bv.x;
    float o1 = (xv.y - mean) * rstd * gv.y + bv.y;
    float o2 = (xv.z - mean) * rstd * gv.z + bv.z;
    float o3 = (xv.w - mean) * rstd * gv.w + bv.w;
    __half* orow = out + (size_t)row * Dm + c;
    *(__half2*)&orow[0] = __floats2half2_rn(o0, o1);
    *(__half2*)&orow[2] = __floats2half2_rn(o2, o3);
}

// ---------------- HMMA fp16 GEMM: C[M,N] = A[M,K] @ W[N,K]^T ----------------
#define NST 3
#define STAGE_BYTES 32768
#define GSMEM (1024 + NST * STAGE_BYTES)

__device__ __forceinline__ float gelu_exact(float v) {
    return 0.5f * v * (1.0f + erff(v * 0.70710678118654752f));
}

template<int MODE, typename TOUT>
__global__ void __launch_bounds__(256, 2)
hgemm_mma(const __half* __restrict__ A, const __half* __restrict__ W,
          const float* __restrict__ bias, const float* __restrict__ resid,
          TOUT* __restrict__ C, int M, int N, int K)
{
    extern __shared__ char dsm[];
    uint32_t stage0 = (smem_u32(dsm) + 1023) & ~1023u;

    int tid  = threadIdx.x;
    int wid  = tid >> 5, lane = tid & 31;
    int wm   = wid & 1;
    int wn   = wid >> 1;
    int rowBase = blockIdx.y * 128;
    int colBase = blockIdx.x * 128;
    int nchunk = K >> 6;

    float acc[4][4][4];
    #pragma unroll
    for (int i = 0; i < 4; i++)
        #pragma unroll
        for (int j = 0; j < 4; j++)
            #pragma unroll
            for (int e = 0; e < 4; e++) acc[i][j][e] = 0.f;

    auto fill = [&](int chunk, int stage) {
        uint32_t sA = stage0 + stage * STAGE_BYTES;
        uint32_t sB = sA + 16384;
        const __half* Ab = A + (size_t)rowBase * K + chunk * 64;
        const __half* Wb = W + (size_t)colBase * K + chunk * 64;
        #pragma unroll
        for (int it = 0; it < 8; it++) {
            int idx = it * 256 + tid;
            int half = idx >> 10;
            int sub  = idx & 1023;
            int r = sub >> 3, c = sub & 7;
            uint32_t off = SWZ(r * 128 + c * 16);
            if (half == 0) cp16(sA + off, Ab + (size_t)r * K + c * 8);
            else           cp16(sB + off, Wb + (size_t)r * K + c * 8);
        }
        CP_COMMIT();
    };

    fill(0, 0);
    fill(1, 1);

    int a_row_off = lane & 15;
    int a_k_off   = (lane >> 4) << 4;
    int b_row_off = (lane & 7) + ((lane >> 4) << 3);
    int b_k_off   = ((lane >> 3) & 1) << 4;

    for (int i = 0; i < nchunk; i++) {
        CP_WAIT1();
        __syncthreads();        // orders cp.async visibility AND stage reuse:
                                // fill(i+2) below writes stage (i-1)%3, whose
                                // readers all passed this barrier.
        if (i + 2 < nchunk) fill(i + 2, (i + 2) % NST);

        uint32_t sA = stage0 + (i % NST) * STAGE_BYTES;
        uint32_t sB = sA + 16384;
        #pragma unroll
        for (int ks = 0; ks < 4; ks++) {
            int kb = ks * 32;
            uint32_t af[4][4], bf[2][4];
            #pragma unroll
            for (int m = 0; m < 4; m++) {
                int row = wm * 64 + m * 16 + a_row_off;
                ldsm4(af[m], sA + SWZ(row * 128 + kb + a_k_off));
            }
            #pragma unroll
            for (int j = 0; j < 2; j++) {
                int row = wn * 32 + j * 16 + b_row_off;
                ldsm4(bf[j], sB + SWZ(row * 128 + kb + b_k_off));
            }
            #pragma unroll
            for (int m = 0; m < 4; m++)
                #pragma unroll
                for (int n = 0; n < 4; n++)
                    mma16816(acc[m][n], af[m], &bf[n >> 1][(n & 1) * 2]);
        }
    }

    int r0 = rowBase + wm * 64 + (lane >> 2);
    int c0 = colBase + wn * 32 + (lane & 3) * 2;
    #pragma unroll
    for (int m = 0; m < 4; m++) {
        #pragma unroll
        for (int n = 0; n < 4; n++) {
            int col = c0 + n * 8;
            float2 bi = make_float2(0.f, 0.f);
            if (MODE >= 1) bi = *(const float2*)&bias[col];
            #pragma unroll
            for (int hrow = 0; hrow < 2; hrow++) {
                int row = r0 + m * 16 + hrow * 8;
                float v0 = acc[m][n][hrow * 2 + 0];
                float v1 = acc[m][n][hrow * 2 + 1];
                if (MODE >= 1) { v0 += bi.x; v1 += bi.y; }
                if (MODE == 1) {
                    float2 rr = *(const float2*)&resid[(size_t)row * N + col];
                    v0 += rr.x; v1 += rr.y;
                }
                if (MODE == 2) { v0 = gelu_exact(v0); v1 = gelu_exact(v1); }
                if (sizeof(TOUT) == 2) {
                    *(__half2*)((__half*)C + (size_t)row * N + col) =
                        __floats2half2_rn(v0, v1);
                } else {
                    *(float2*)((float*)C + (size_t)row * N + col) =
                        make_float2(v0, v1);
                }
            }
        }
    }
}

// ---------------- HMMA flash attention (dense q/k/v, stride Dm) ----------
// CTA: 128 threads (4 warps), 64 q-rows. K/V streamed in 64-row tiles,
// double-buffered. smem: Q 8KB | 2 x (K 8KB + V 8KB) | mask 8KB = 48KB.
#define ATTN_SMEM (8192 + 2 * 16384 + 8192)

__global__ void __launch_bounds__(128) attn_mma(
    const __half* __restrict__ q, const __half* __restrict__ k,
    const __half* __restrict__ v, const float* __restrict__ pm,
    __half* __restrict__ out)
{
    extern __shared__ char smraw[];
    uint32_t base = smem_u32(smraw);
    float* Msk = (float*)(smraw + 8192 + 32768);

    int tid = threadIdx.x, wid = tid >> 5, lane = tid & 31;
    int qtile = blockIdx.x, bh = blockIdx.y;
    int b = bh >> 4, h = bh & 15;
    int q0 = qtile * 64;

    const __half* qb = q + ((size_t)b * Sq) * Dm + h * HDm;
    const __half* kb = k + ((size_t)b * Sq) * Dm + h * HDm;
    const __half* vb = v + ((size_t)b * Sq) * Dm + h * HDm;

    // mask -> smem (pre-transformed additive bias)
    {
        const float4* pmb = (const float4*)(pm + (size_t)b * Sq);
        for (int i = tid; i < Sq / 4; i += 128) {
            float4 mv = pmb[i];
            float4 w;
            w.x = (1.f - mv.x) * -10000.f; w.y = (1.f - mv.y) * -10000.f;
            w.z = (1.f - mv.z) * -10000.f; w.w = (1.f - mv.w) * -10000.f;
            ((float4*)Msk)[i] = w;
        }
    }

    // Q tile -> smem (group 0)
    #pragma unroll
    for (int it = 0; it < 4; it++) {
        int idx = it * 128 + tid;
        int r = idx >> 3, c = idx & 7;
        cp16(base + SWZ(r * 128 + c * 16), qb + (size_t)(q0 + r) * Dm + c * 8);
    }
    CP_COMMIT();

    auto fillkv = [&](int kt, int st) {
        uint32_t sK = base + 8192 + st * 16384;
        uint32_t sV = sK + 8192;
        int k0 = kt * 64;
        #pragma unroll
        for (int it = 0; it < 8; it++) {
            int idx = it * 128 + tid;
            int hf = idx >> 9, sub = idx & 511;
            int r = sub >> 3, c = sub & 7;
            uint32_t off = SWZ(r * 128 + c * 16);
            if (hf == 0) cp16(sK + off, kb + (size_t)(k0 + r) * Dm + c * 8);
            else         cp16(sV + off, vb + (size_t)(k0 + r) * Dm + c * 8);
        }
        CP_COMMIT();
    };
    fillkv(0, 0);

    CP_WAIT1();                 // Q tile resident (kv0 may still be in flight)
    __syncthreads();

    int a_row = lane & 15, a_kb = (lane >> 4) << 4;
    int b_row = (lane & 7) + ((lane >> 4) << 3);
    int b_kb  = ((lane >> 3) & 1) << 4;
    int colb  = (lane & 3) * 2;

    uint32_t qf[4][4];
    #pragma unroll
    for (int ks = 0; ks < 4; ks++)
        ldsm4(qf[ks], base + SWZ((wid * 16 + a_row) * 128 + ks * 32 + a_kb));

    float m_[2] = {-1e30f, -1e30f}, l_[2] = {0.f, 0.f};
    float o[8][4];
    #pragma unroll
    for (int nb = 0; nb < 8; nb++)
        #pragma unroll
        for (int e = 0; e < 4; e++) o[nb][e] = 0.f;

    for (int kt = 0; kt < Sq / 64; kt++) {
        int st = kt & 1;
        if (kt + 1 < Sq / 64) { fillkv(kt + 1, st ^ 1); CP_WAIT1(); }
        else                  { CP_WAIT0(); }
        __syncthreads();
        uint32_t sK = base + 8192 + st * 16384;
        uint32_t sV = sK + 8192;
        int k0 = kt * 64;

        // S = Q @ K^T
        float sc[8][4];
        #pragma unroll
        for (int nb = 0; nb < 8; nb++)
            #pragma unroll
            for (int e = 0; e < 4; e++) sc[nb][e] = 0.f;
        #pragma unroll
        for (int np = 0; np < 4; np++) {
            #pragma unroll
            for (int ks = 0; ks < 4; ks++) {
                uint32_t bf[4];
                ldsm4(bf, sK + SWZ((np * 16 + b_row) * 128 + ks * 32 + b_kb));
                mma16816(sc[2 * np],     qf[ks], &bf[0]);
                mma16816(sc[2 * np + 1], qf[ks], &bf[2]);
            }
        }

        // scale + mask + online softmax (fast exp on FMA pipe)
        float ml0 = -1e30f, ml1 = -1e30f;
        #pragma unroll
        for (int nb = 0; nb < 8; nb++) {
            float mk0 = Msk[k0 + nb * 8 + colb];
            float mk1 = Msk[k0 + nb * 8 + colb + 1];
            sc[nb][0] = fmaf(sc[nb][0], 0.125f, mk0);
            sc[nb][1] = fmaf(sc[nb][1], 0.125f, mk1);
            sc[nb][2] = fmaf(sc[nb][2], 0.125f, mk0);
            sc[nb][3] = fmaf(sc[nb][3], 0.125f, mk1);
            ml0 = fmaxf(ml0, fmaxf(sc[nb][0], sc[nb][1]));
            ml1 = fmaxf(ml1, fmaxf(sc[nb][2], sc[nb][3]));
        }
        ml0 = fmaxf(ml0, __shfl_xor_sync(0xffffffffu, ml0, 1));
        ml0 = fmaxf(ml0, __shfl_xor_sync(0xffffffffu, ml0, 2));
        ml1 = fmaxf(ml1, __shfl_xor_sync(0xffffffffu, ml1, 1));
        ml1 = fmaxf(ml1, __shfl_xor_sync(0xffffffffu, ml1, 2));
        float mn0 = fmaxf(m_[0], ml0), mn1 = fmaxf(m_[1], ml1);
        float al0 = fexp2n((m_[0] - mn0) * L2E);
        float al1 = fexp2n((m_[1] - mn1) * L2E);
        float bb0 = mn0 * L2E, bb1 = mn1 * L2E;
        float s0 = 0.f, s1 = 0.f;
        #pragma unroll
        for (int nb = 0; nb < 8; nb++) {
            sc[nb][0] = fexp2n(fmaf(sc[nb][0], L2E, -bb0));
            sc[nb][1] = fexp2n(fmaf(sc[nb][1], L2E, -bb0));
            sc[nb][2] = fexp2n(fmaf(sc[nb][2], L2E, -bb1));
            sc[nb][3] = fexp2n(fmaf(sc[nb][3], L2E, -bb1));
            s0 += sc[nb][0] + sc[nb][1];
            s1 += sc[nb][2] + sc[nb][3];
        }
        s0 += __shfl_xor_sync(0xffffffffu, s0, 1);
        s0 += __shfl_xor_sync(0xffffffffu, s0, 2);
        s1 += __shfl_xor_sync(0xffffffffu, s1, 1);
        s1 += __shfl_xor_sync(0xffffffffu, s1, 2);
        l_[0] = l_[0] * al0 + s0; l_[1] = l_[1] * al1 + s1;
        m_[0] = mn0; m_[1] = mn1;
        #pragma unroll
        for (int nb = 0; nb < 8; nb++) {
            o[nb][0] *= al0; o[nb][1] *= al0;
            o[nb][2] *= al1; o[nb][3] *= al1;
        }

        // O += P @ V  (P stays in registers: S-accum layout == A-frag layout)
        #pragma unroll
        for (int ks = 0; ks < 4; ks++) {
            uint32_t pa[4];
            __half2 p0 = __floats2half2_rn(sc[2*ks][0],   sc[2*ks][1]);
            __half2 p1 = __floats2half2_rn(sc[2*ks][2],   sc[2*ks][3]);
            __half2 p2 = __floats2half2_rn(sc[2*ks+1][0], sc[2*ks+1][1]);
            __half2 p3 = __floats2half2_rn(sc[2*ks+1][2], sc[2*ks+1][3]);
            pa[0] = *(uint32_t*)&p0; pa[1] = *(uint32_t*)&p1;
            pa[2] = *(uint32_t*)&p2; pa[3] = *(uint32_t*)&p3;
            #pragma unroll
            for (int np = 0; np < 4; np++) {
                uint32_t vf[4];
                ldsm4t(vf, sV + SWZ((ks * 16 + a_row) * 128 + np * 32 + a_kb));
                mma16816(o[2 * np],     pa, &vf[0]);
                mma16816(o[2 * np + 1], pa, &vf[2]);
            }
        }
        __syncthreads();
    }

    float inv0 = 1.f / l_[0], inv1 = 1.f / l_[1];
    int r0g = q0 + wid * 16 + (lane >> 2);
    __half* ob = out + ((size_t)b * Sq) * Dm + h * HDm;
    #pragma unroll
    for (int nb = 0; nb < 8; nb++) {
        int col = nb * 8 + colb;
        *(__half2*)&ob[(size_t)r0g * Dm + col] =
            __floats2half2_rn(o[nb][0] * inv0, o[nb][1] * inv0);
        *(__half2*)&ob[(size_t)(r0g + 8) * Dm + col] =
            __floats2half2_rn(o[nb][2] * inv1, o[nb][3] * inv1);
    }
}

// ---------------- launch ----------------
extern "C" void kernel_launch(void* const* d_in, const int* in_sizes, int n_in,
                              void* d_out, int out_size) {
    const float* x     = (const float*)d_in[0];
    const float* pmask = (const float*)d_in[1];
    const float* Wq    = (const float*)d_in[2];
    const float* Wk    = (const float*)d_in[3];
    const float* Wv    = (const float*)d_in[4];
    const float* Wu    = (const float*)d_in[5];
    const float* bu    = (const float*)d_in[6];
    const float* W1    = (const float*)d_in[7];
    const float* b1    = (const float*)d_in[8];
    const float* W2    = (const float*)d_in[9];
    const float* b2    = (const float*)d_in[10];
    const float* g1    = (const float*)d_in[11];
    const float* be1   = (const float*)d_in[12];
    const float* g2    = (const float*)d_in[13];
    const float* be2   = (const float*)d_in[14];
    float* out = (float*)d_out;

    __half *xn16, *q16, *k16, *v16, *ao16, *xm16, *h16;
    __half *wqkv16, *wu16, *w116, *w216;
    float *x1;
    cudaGetSymbolAddress((void**)&xn16,   g_xn16);
    cudaGetSymbolAddress((void**)&q16,    g_q16);
    cudaGetSymbolAddress((void**)&k16,    g_k16);
    cudaGetSymbolAddress((void**)&v16,    g_v16);
    cudaGetSymbolAddress((void**)&ao16,   g_ao16);
    cudaGetSymbolAddress((void**)&x1,     g_x1);
    cudaGetSymbolAddress((void**)&xm16,   g_xm16);
    cudaGetSymbolAddress((void**)&h16,    g_h16);
    cudaGetSymbolAddress((void**)&wqkv16, g_wqkv16);
    cudaGetSymbolAddress((void**)&wu16,   g_wu16);
    cudaGetSymbolAddress((void**)&w116,   g_w116);
    cudaGetSymbolAddress((void**)&w216,   g_w216);

    __half* wq16 = wqkv16;
    __half* wk16 = wqkv16 + Dm * Dm;
    __half* wv16 = wqkv16 + 2 * Dm * Dm;

    cudaFuncSetAttribute(attn_mma, cudaFuncAttributeMaxDynamicSharedMemorySize,
                         ATTN_SMEM);
    cudaFuncSetAttribute(hgemm_mma<0, __half>,
                         cudaFuncAttributeMaxDynamicSharedMemorySize, GSMEM);
    cudaFuncSetAttribute(hgemm_mma<1, float>,
                         cudaFuncAttributeMaxDynamicSharedMemorySize, GSMEM);
    cudaFuncSetAttribute(hgemm_mma<2, __half>,
                         cudaFuncAttributeMaxDynamicSharedMemorySize, GSMEM);

    // fused weight conversion (8M elements, one launch)
    f2h_all<<<8192, 256>>>(Wq, Wk, Wv, Wu, W1, W2);

    dim3 gD(Dm / 128, ROWS / 128);    // (8, 64)
    dim3 gF(FFm / 128, ROWS / 128);   // (16, 64)

    ln_kernel<<<ROWS, 256>>>(x, g1, be1, xn16);

    hgemm_mma<0, __half><<<gD, 256, GSMEM>>>(xn16, wq16, nullptr, nullptr, q16, ROWS, Dm, Dm);
    hgemm_mma<0, __half><<<gD, 256, GSMEM>>>(xn16, wk16, nullptr, nullptr, k16, ROWS, Dm, Dm);
    hgemm_mma<0, __half><<<gD, 256, GSMEM>>>(xn16, wv16, nullptr, nullptr, v16, ROWS, Dm, Dm);

    attn_mma<<<dim3(Sq / 64, Bsz * Hn), 128, ATTN_SMEM>>>(q16, k16, v16, pmask, ao16);

    hgemm_mma<1, float><<<gD, 256, GSMEM>>>(ao16, wu16, bu, x, x1, ROWS, Dm, Dm);

    ln_kernel<<<ROWS, 256>>>(x1, g2, be2, xm16);

    hgemm_mma<2, __half><<<gF, 256, GSMEM>>>(xm16, w116, b1, nullptr, h16, ROWS, FFm, Dm);

    hgemm_mma<1, float><<<gD, 256, GSMEM>>>(h16, w216, b2, x1, out, ROWS, Dm, FFm);
}

// round 13
// speedup vs baseline: 1.6466x; 1.0917x over previous
#include <cuda_runtime.h>
#include <cuda_fp16.h>
#include <math.h>
#include <stdint.h>

#define Bsz 4
#define Sq  2048
#define Dm  1024
#define Hn  16
#define HDm 64
#define FFm 2048
#define ROWS (Bsz * Sq)   // 8192

// ---------------- scratch (no allocations allowed) ----------------
__device__ __half g_xn16[ROWS * Dm];
__device__ __half g_q16[ROWS * Dm];
__device__ __half g_k16[ROWS * Dm];
__device__ __half g_v16[ROWS * Dm];
__device__ __half g_ao16[ROWS * Dm];
__device__ float  g_x1[ROWS * Dm];
__device__ __half g_xm16[ROWS * Dm];
__device__ __half g_h16[ROWS * FFm];
__device__ __half g_wqkv16[3 * Dm * Dm];   // Wq | Wk | Wv segments (fused N=3072)
__device__ __half g_wu16[Dm * Dm];
__device__ __half g_w116[FFm * Dm];
__device__ __half g_w216[Dm * FFm];

// ---------------- PTX helpers (sm_80-portable only!) ----------------
__device__ __forceinline__ uint32_t smem_u32(const void* p) {
    uint32_t a;
    asm("{ .reg .u64 t; cvta.to.shared.u64 t, %1; cvt.u32.u64 %0, t; }"
        : "=r"(a) : "l"(p));
    return a;
}
__device__ __forceinline__ void cp16(uint32_t saddr, const void* gaddr) {
    asm volatile("cp.async.cg.shared.global [%0], [%1], 16;"
                 :: "r"(saddr), "l"(gaddr));
}
#define CP_COMMIT() asm volatile("cp.async.commit_group;" ::: "memory")
#define CP_WAIT1()  asm volatile("cp.async.wait_group 1;" ::: "memory")
#define CP_WAIT0()  asm volatile("cp.async.wait_group 0;" ::: "memory")
#define SWZ(o) ((o) ^ (((o) >> 3) & 0x70))

__device__ __forceinline__ void ldsm4(uint32_t* r, uint32_t addr) {
    asm volatile("ldmatrix.sync.aligned.m8n8.x4.shared.b16 {%0,%1,%2,%3}, [%4];"
                 : "=r"(r[0]), "=r"(r[1]), "=r"(r[2]), "=r"(r[3]) : "r"(addr));
}
__device__ __forceinline__ void ldsm4t(uint32_t* r, uint32_t addr) {
    asm volatile("ldmatrix.sync.aligned.m8n8.x4.trans.shared.b16 {%0,%1,%2,%3}, [%4];"
                 : "=r"(r[0]), "=r"(r[1]), "=r"(r[2]), "=r"(r[3]) : "r"(addr));
}
__device__ __forceinline__ void mma16816(float* c, const uint32_t* a,
                                         const uint32_t* b) {
    asm volatile("mma.sync.aligned.m16n8k16.row.col.f32.f16.f16.f32 "
                 "{%0,%1,%2,%3}, {%4,%5,%6,%7}, {%8,%9}, {%0,%1,%2,%3};"
                 : "+f"(c[0]), "+f"(c[1]), "+f"(c[2]), "+f"(c[3])
                 : "r"(a[0]), "r"(a[1]), "r"(a[2]), "r"(a[3]),
                   "r"(b[0]), "r"(b[1]));
}

// fast float 2^y (y <= 0 expected; clamped). rel err ~1e-6. Used only for alpha.
#define L2E 1.4426950408889634f
__device__ __forceinline__ float fexp2n(float y) {
    y = fmaxf(y, -125.f);
    float t = y + 12582912.f;               // 1.5 * 2^23 rounding trick
    int n = __float_as_int(t) - 0x4B400000;
    float f = y - (t - 12582912.f);         // f in [-0.5, 0.5]
    float p = 1.f + f * (0.693147182f + f * (0.240226507f + f * (0.0555041087f
              + f * (0.00961812911f + f * 0.00133335581f))));
    return __int_as_float(__float_as_int(p) + (n << 23));
}

// half2 SIMD 2^y for y in (-inf, ~0]; clamps at -14 (exp2(-14)~6e-5 ~ 0).
// 1536-offset trick; per-lane exponent injection via one 32-bit sub+shl
// (lane values <= 0x3C00, so the shift never spills across lanes).
// (named to avoid collision with cuda_fp16.hpp's h2exp2)
__device__ __forceinline__ __half2 h2exp2f_(__half2 y) {
    y = __hmax2(y, __float2half2_rn(-14.f));
    const __half2 c1536 = __float2half2_rn(1536.f);
    __half2 t = __hadd2(y, c1536);
    __half2 f = __hsub2(y, __hsub2(t, c1536));     // f in [-0.5, 0.5]
    uint32_t sb = ((*(uint32_t*)&t) - 0x65F165F1u) << 10;  // 2^n per lane
    __half2 scale = *(__half2*)&sb;
    __half2 p = __hfma2(f, __float2half2_rn(0.05550411f),
                           __float2half2_rn(0.24022651f));
    p = __hfma2(f, p, __float2half2_rn(0.69314718f));
    p = __hfma2(f, p, __float2half2_rn(1.0f));
    return __hmul2(p, scale);
}

// ---------------- fused fp32 -> fp16 weight conversion ----------------
__global__ void __launch_bounds__(256) f2h_all(
    const float* __restrict__ Wq, const float* __restrict__ Wk,
    const float* __restrict__ Wv, const float* __restrict__ Wu,
    const float* __restrict__ W1, const float* __restrict__ W2)
{
    int v4 = blockIdx.x * 256 + threadIdx.x;   // 0 .. 2M-1
    const float* src;
    __half* dst;
    int base;
    if      (v4 <  262144) { src = Wq; dst = g_wqkv16;               base = 0; }
    else if (v4 <  524288) { src = Wk; dst = g_wqkv16 + 1048576;     base = 262144; }
    else if (v4 <  786432) { src = Wv; dst = g_wqkv16 + 2097152;     base = 524288; }
    else if (v4 < 1048576) { src = Wu; dst = g_wu16;                 base = 786432; }
    else if (v4 < 1572864) { src = W1; dst = g_w116;                 base = 1048576; }
    else                   { src = W2; dst = g_w216;                 base = 1572864; }
    int i = (v4 - base) * 4;
    float4 v = *(const float4*)&src[i];
    *(__half2*)&dst[i]     = __floats2half2_rn(v.x, v.y);
    *(__half2*)&dst[i + 2] = __floats2half2_rn(v.z, v.w);
}

// ---------------- LayerNorm (fp32 in, fp16 out) ----------------
__global__ void __launch_bounds__(256) ln_kernel(const float* __restrict__ x,
                                                 const float* __restrict__ g,
                                                 const float* __restrict__ b,
                                                 __half* __restrict__ out) {
    int row = blockIdx.x;
    const float* xr = x + (size_t)row * Dm;
    int c = threadIdx.x * 4;
    float4 xv = *(const float4*)&xr[c];
    float s  = xv.x + xv.y + xv.z + xv.w;
    float ss = xv.x*xv.x + xv.y*xv.y + xv.z*xv.z + xv.w*xv.w;
    #pragma unroll
    for (int m = 16; m > 0; m >>= 1) {
        s  += __shfl_xor_sync(0xffffffffu, s,  m);
        ss += __shfl_xor_sync(0xffffffffu, ss, m);
    }
    __shared__ float sred[16];
    int w = threadIdx.x >> 5, lane = threadIdx.x & 31;
    if (lane == 0) { sred[w] = s; sred[w + 8] = ss; }
    __syncthreads();
    float tot = 0.f, tot2 = 0.f;
    #pragma unroll
    for (int i = 0; i < 8; i++) { tot += sred[i]; tot2 += sred[8 + i]; }
    float mean = tot * (1.0f / Dm);
    float var  = tot2 * (1.0f / Dm) - mean * mean;
    float rstd = rsqrtf(var + 1e-5f);
    float4 gv = *(const float4*)&g[c];
    float4 bv = *(const float4*)&b[c];
    float o0 = (xv.x - mean) * rstd * gv.x + bv.x;
    float o1 = (xv.y - mean) * rstd * gv.y + bv.y;
    float o2 = (xv.z - mean) * rstd * gv.z + bv.z;
    float o3 = (xv.w - mean) * rstd * gv.w + bv.w;
    __half* orow = out + (size_t)row * Dm + c;
    *(__half2*)&orow[0] = __floats2half2_rn(o0, o1);
    *(__half2*)&orow[2] = __floats2half2_rn(o2, o3);
}

// ---------------- HMMA fp16 GEMM: C[M,N] = A[M,K] @ W[N,K]^T ----------------
// MODE 0: plain  MODE 1: +bias+residual (float out)  MODE 2: gelu(.+bias)
// QKV=1: N=3072 fused; output column block colBase>>10 selects C/C2/C3,
//        each a dense [M, Dm] buffer (keeps attention reads stride-Dm).
#define NST 3
#define STAGE_BYTES 32768
#define GSMEM (1024 + NST * STAGE_BYTES)

__device__ __forceinline__ float gelu_exact(float v) {
    return 0.5f * v * (1.0f + erff(v * 0.70710678118654752f));
}

template<int MODE, int QKV, typename TOUT>
__global__ void __launch_bounds__(256, 2)
hgemm_mma(const __half* __restrict__ A, const __half* __restrict__ W,
          const float* __restrict__ bias, const float* __restrict__ resid,
          TOUT* __restrict__ C, TOUT* __restrict__ C2, TOUT* __restrict__ C3,
          int M, int N, int K)
{
    extern __shared__ char dsm[];
    uint32_t stage0 = (smem_u32(dsm) + 1023) & ~1023u;

    int tid  = threadIdx.x;
    int wid  = tid >> 5, lane = tid & 31;
    int wm   = wid & 1;
    int wn   = wid >> 1;
    int rowBase = blockIdx.y * 128;
    int colBase = blockIdx.x * 128;
    int nchunk = K >> 6;

    TOUT* Cd = C;
    if (QKV) {
        int mi = colBase >> 10;
        Cd = (mi == 0) ? C : ((mi == 1) ? C2 : C3);
    }
    const int strideO = QKV ? Dm : N;

    float acc[4][4][4];
    #pragma unroll
    for (int i = 0; i < 4; i++)
        #pragma unroll
        for (int j = 0; j < 4; j++)
            #pragma unroll
            for (int e = 0; e < 4; e++) acc[i][j][e] = 0.f;

    auto fill = [&](int chunk, int stage) {
        uint32_t sA = stage0 + stage * STAGE_BYTES;
        uint32_t sB = sA + 16384;
        const __half* Ab = A + (size_t)rowBase * K + chunk * 64;
        const __half* Wb = W + (size_t)colBase * K + chunk * 64;
        #pragma unroll
        for (int it = 0; it < 8; it++) {
            int idx = it * 256 + tid;
            int half = idx >> 10;
            int sub  = idx & 1023;
            int r = sub >> 3, c = sub & 7;
            uint32_t off = SWZ(r * 128 + c * 16);
            if (half == 0) cp16(sA + off, Ab + (size_t)r * K + c * 8);
            else           cp16(sB + off, Wb + (size_t)r * K + c * 8);
        }
        CP_COMMIT();
    };

    fill(0, 0);
    fill(1, 1);

    int a_row_off = lane & 15;
    int a_k_off   = (lane >> 4) << 4;
    int b_row_off = (lane & 7) + ((lane >> 4) << 3);
    int b_k_off   = ((lane >> 3) & 1) << 4;

    for (int i = 0; i < nchunk; i++) {
        CP_WAIT1();
        __syncthreads();        // orders cp.async visibility AND stage reuse
        if (i + 2 < nchunk) fill(i + 2, (i + 2) % NST);

        uint32_t sA = stage0 + (i % NST) * STAGE_BYTES;
        uint32_t sB = sA + 16384;
        #pragma unroll
        for (int ks = 0; ks < 4; ks++) {
            int kb = ks * 32;
            uint32_t af[4][4], bf[2][4];
            #pragma unroll
            for (int m = 0; m < 4; m++) {
                int row = wm * 64 + m * 16 + a_row_off;
                ldsm4(af[m], sA + SWZ(row * 128 + kb + a_k_off));
            }
            #pragma unroll
            for (int j = 0; j < 2; j++) {
                int row = wn * 32 + j * 16 + b_row_off;
                ldsm4(bf[j], sB + SWZ(row * 128 + kb + b_k_off));
            }
            #pragma unroll
            for (int m = 0; m < 4; m++)
                #pragma unroll
                for (int n = 0; n < 4; n++)
                    mma16816(acc[m][n], af[m], &bf[n >> 1][(n & 1) * 2]);
        }
    }

    int r0 = rowBase + wm * 64 + (lane >> 2);
    int c0 = colBase + wn * 32 + (lane & 3) * 2;
    #pragma unroll
    for (int m = 0; m < 4; m++) {
        #pragma unroll
        for (int n = 0; n < 4; n++) {
            int col = c0 + n * 8;
            int cw  = QKV ? (col & 1023) : col;
            float2 bi = make_float2(0.f, 0.f);
            if (MODE >= 1) bi = *(const float2*)&bias[col];
            #pragma unroll
            for (int hrow = 0; hrow < 2; hrow++) {
                int row = r0 + m * 16 + hrow * 8;
                float v0 = acc[m][n][hrow * 2 + 0];
                float v1 = acc[m][n][hrow * 2 + 1];
                if (MODE >= 1) { v0 += bi.x; v1 += bi.y; }
                if (MODE == 1) {
                    float2 rr = *(const float2*)&resid[(size_t)row * N + col];
                    v0 += rr.x; v1 += rr.y;
                }
                if (MODE == 2) { v0 = gelu_exact(v0); v1 = gelu_exact(v1); }
                if (sizeof(TOUT) == 2) {
                    *(__half2*)((__half*)Cd + (size_t)row * strideO + cw) =
                        __floats2half2_rn(v0, v1);
                } else {
                    *(float2*)((float*)Cd + (size_t)row * strideO + cw) =
                        make_float2(v0, v1);
                }
            }
        }
    }
}

// ---------------- HMMA flash attention (dense q/k/v, stride Dm) ----------
// CTA: 128 threads (4 warps), 64 q-rows. K/V streamed in 64-row tiles,
// double-buffered. smem: Q 8KB | 2 x (K 8KB + V 8KB) | mask 8KB = 48KB.
// Softmax runs in log2 domain; exp evaluated in half2 SIMD (results ARE the
// P fragments for the P@V mma — no separate pack step).
#define ATTN_SMEM (8192 + 2 * 16384 + 8192)

__global__ void __launch_bounds__(128) attn_mma(
    const __half* __restrict__ q, const __half* __restrict__ k,
    const __half* __restrict__ v, const float* __restrict__ pm,
    __half* __restrict__ out)
{
    extern __shared__ char smraw[];
    uint32_t base = smem_u32(smraw);
    float* Msk = (float*)(smraw + 8192 + 32768);

    int tid = threadIdx.x, wid = tid >> 5, lane = tid & 31;
    int qtile = blockIdx.x, bh = blockIdx.y;
    int b = bh >> 4, h = bh & 15;
    int q0 = qtile * 64;

    const __half* qb = q + ((size_t)b * Sq) * Dm + h * HDm;
    const __half* kb = k + ((size_t)b * Sq) * Dm + h * HDm;
    const __half* vb = v + ((size_t)b * Sq) * Dm + h * HDm;

    // mask -> smem: additive bias pre-scaled by log2(e) (log2-domain softmax)
    {
        const float4* pmb = (const float4*)(pm + (size_t)b * Sq);
        const float MB = -10000.f * L2E;
        for (int i = tid; i < Sq / 4; i += 128) {
            float4 mv = pmb[i];
            float4 w;
            w.x = (1.f - mv.x) * MB; w.y = (1.f - mv.y) * MB;
            w.z = (1.f - mv.z) * MB; w.w = (1.f - mv.w) * MB;
            ((float4*)Msk)[i] = w;
        }
    }

    // Q tile -> smem (group 0)
    #pragma unroll
    for (int it = 0; it < 4; it++) {
        int idx = it * 128 + tid;
        int r = idx >> 3, c = idx & 7;
        cp16(base + SWZ(r * 128 + c * 16), qb + (size_t)(q0 + r) * Dm + c * 8);
    }
    CP_COMMIT();

    auto fillkv = [&](int kt, int st) {
        uint32_t sK = base + 8192 + st * 16384;
        uint32_t sV = sK + 8192;
        int k0 = kt * 64;
        #pragma unroll
        for (int it = 0; it < 8; it++) {
            int idx = it * 128 + tid;
            int hf = idx >> 9, sub = idx & 511;
            int r = sub >> 3, c = sub & 7;
            uint32_t off = SWZ(r * 128 + c * 16);
            if (hf == 0) cp16(sK + off, kb + (size_t)(k0 + r) * Dm + c * 8);
            else         cp16(sV + off, vb + (size_t)(k0 + r) * Dm + c * 8);
        }
        CP_COMMIT();
    };
    fillkv(0, 0);

    CP_WAIT1();                 // Q tile resident (kv0 may still be in flight)
    __syncthreads();

    int a_row = lane & 15, a_kb = (lane >> 4) << 4;
    int b_row = (lane & 7) + ((lane >> 4) << 3);
    int b_kb  = ((lane >> 3) & 1) << 4;
    int colb  = (lane & 3) * 2;

    uint32_t qf[4][4];
    #pragma unroll
    for (int ks = 0; ks < 4; ks++)
        ldsm4(qf[ks], base + SWZ((wid * 16 + a_row) * 128 + ks * 32 + a_kb));

    float m_[2] = {-1e30f, -1e30f}, l_[2] = {0.f, 0.f};
    float o[8][4];
    #pragma unroll
    for (int nb = 0; nb < 8; nb++)
        #pragma unroll
        for (int e = 0; e < 4; e++) o[nb][e] = 0.f;

    const float CSC = 0.125f * L2E;     // score scale folded with log2(e)

    for (int kt = 0; kt < Sq / 64; kt++) {
        int st = kt & 1;
        if (kt + 1 < Sq / 64) { fillkv(kt + 1, st ^ 1); CP_WAIT1(); }
        else                  { CP_WAIT0(); }
        __syncthreads();
        uint32_t sK = base + 8192 + st * 16384;
        uint32_t sV = sK + 8192;
        int k0 = kt * 64;

        // S = Q @ K^T
        float sc[8][4];
        #pragma unroll
        for (int nb = 0; nb < 8; nb++)
            #pragma unroll
            for (int e = 0; e < 4; e++) sc[nb][e] = 0.f;
        #pragma unroll
        for (int np = 0; np < 4; np++) {
            #pragma unroll
            for (int ks = 0; ks < 4; ks++) {
                uint32_t bf[4];
                ldsm4(bf, sK + SWZ((np * 16 + b_row) * 128 + ks * 32 + b_kb));
                mma16816(sc[2 * np],     qf[ks], &bf[0]);
                mma16816(sc[2 * np + 1], qf[ks], &bf[2]);
            }
        }

        // log2-domain scores -> half2 pairs; row max via hmax2
        __half2 ps0[8], ps1[8];
        __half2 ymax0 = __float2half2_rn(-60000.f);
        __half2 ymax1 = ymax0;
        #pragma unroll
        for (int nb = 0; nb < 8; nb++) {
            float mk0 = Msk[k0 + nb * 8 + colb];
            float mk1 = Msk[k0 + nb * 8 + colb + 1];
            ps0[nb] = __floats2half2_rn(fmaf(sc[nb][0], CSC, mk0),
                                        fmaf(sc[nb][1], CSC, mk1));
            ps1[nb] = __floats2half2_rn(fmaf(sc[nb][2], CSC, mk0),
                                        fmaf(sc[nb][3], CSC, mk1));
            ymax0 = __hmax2(ymax0, ps0[nb]);
            ymax1 = __hmax2(ymax1, ps1[nb]);
        }
        float ml0 = fmaxf(__low2float(ymax0), __high2float(ymax0));
        float ml1 = fmaxf(__low2float(ymax1), __high2float(ymax1));
        ml0 = fmaxf(ml0, __shfl_xor_sync(0xffffffffu, ml0, 1));
        ml0 = fmaxf(ml0, __shfl_xor_sync(0xffffffffu, ml0, 2));
        ml1 = fmaxf(ml1, __shfl_xor_sync(0xffffffffu, ml1, 1));
        ml1 = fmaxf(ml1, __shfl_xor_sync(0xffffffffu, ml1, 2));
        float mn0 = fmaxf(m_[0], ml0), mn1 = fmaxf(m_[1], ml1);
        float al0 = fexp2n(m_[0] - mn0);
        float al1 = fexp2n(m_[1] - mn1);
        __half2 mh0 = __float2half2_rn(mn0), mh1 = __float2half2_rn(mn1);

        // P = 2^(y - mn) in half2 (directly usable as mma A-fragments)
        float s0 = 0.f, s1 = 0.f;
        #pragma unroll
        for (int nb = 0; nb < 8; nb++) {
            ps0[nb] = h2exp2f_(__hsub2(ps0[nb], mh0));
            ps1[nb] = h2exp2f_(__hsub2(ps1[nb], mh1));
            s0 += __half2float(__hadd(__low2half(ps0[nb]), __high2half(ps0[nb])));
            s1 += __half2float(__hadd(__low2half(ps1[nb]), __high2half(ps1[nb])));
        }
        s0 += __shfl_xor_sync(0xffffffffu, s0, 1);
        s0 += __shfl_xor_sync(0xffffffffu, s0, 2);
        s1 += __shfl_xor_sync(0xffffffffu, s1, 1);
        s1 += __shfl_xor_sync(0xffffffffu, s1, 2);
        l_[0] = l_[0] * al0 + s0; l_[1] = l_[1] * al1 + s1;
        m_[0] = mn0; m_[1] = mn1;
        #pragma unroll
        for (int nb = 0; nb < 8; nb++) {
            o[nb][0] *= al0; o[nb][1] *= al0;
            o[nb][2] *= al1; o[nb][3] *= al1;
        }

        // O += P @ V  (ps0/ps1 are already the packed A-fragments)
        #pragma unroll
        for (int ks = 0; ks < 4; ks++) {
            uint32_t pa[4];
            pa[0] = *(uint32_t*)&ps0[2 * ks];
            pa[1] = *(uint32_t*)&ps1[2 * ks];
            pa[2] = *(uint32_t*)&ps0[2 * ks + 1];
            pa[3] = *(uint32_t*)&ps1[2 * ks + 1];
            #pragma unroll
            for (int np = 0; np < 4; np++) {
                uint32_t vf[4];
                ldsm4t(vf, sV + SWZ((ks * 16 + a_row) * 128 + np * 32 + a_kb));
                mma16816(o[2 * np],     pa, &vf[0]);
                mma16816(o[2 * np + 1], pa, &vf[2]);
            }
        }
        __syncthreads();
    }

    float inv0 = 1.f / l_[0], inv1 = 1.f / l_[1];
    int r0g = q0 + wid * 16 + (lane >> 2);
    __half* ob = out + ((size_t)b * Sq) * Dm + h * HDm;
    #pragma unroll
    for (int nb = 0; nb < 8; nb++) {
        int col = nb * 8 + colb;
        *(__half2*)&ob[(size_t)r0g * Dm + col] =
            __floats2half2_rn(o[nb][0] * inv0, o[nb][1] * inv0);
        *(__half2*)&ob[(size_t)(r0g + 8) * Dm + col] =
            __floats2half2_rn(o[nb][2] * inv1, o[nb][3] * inv1);
    }
}

// ---------------- launch ----------------
extern "C" void kernel_launch(void* const* d_in, const int* in_sizes, int n_in,
                              void* d_out, int out_size) {
    const float* x     = (const float*)d_in[0];
    const float* pmask = (const float*)d_in[1];
    const float* Wq    = (const float*)d_in[2];
    const float* Wk    = (const float*)d_in[3];
    const float* Wv    = (const float*)d_in[4];
    const float* Wu    = (const float*)d_in[5];
    const float* bu    = (const float*)d_in[6];
    const float* W1    = (const float*)d_in[7];
    const float* b1    = (const float*)d_in[8];
    const float* W2    = (const float*)d_in[9];
    const float* b2    = (const float*)d_in[10];
    const float* g1    = (const float*)d_in[11];
    const float* be1   = (const float*)d_in[12];
    const float* g2    = (const float*)d_in[13];
    const float* be2   = (const float*)d_in[14];
    float* out = (float*)d_out;

    __half *xn16, *q16, *k16, *v16, *ao16, *xm16, *h16;
    __half *wqkv16, *wu16, *w116, *w216;
    float *x1;
    cudaGetSymbolAddress((void**)&xn16,   g_xn16);
    cudaGetSymbolAddress((void**)&q16,    g_q16);
    cudaGetSymbolAddress((void**)&k16,    g_k16);
    cudaGetSymbolAddress((void**)&v16,    g_v16);
    cudaGetSymbolAddress((void**)&ao16,   g_ao16);
    cudaGetSymbolAddress((void**)&x1,     g_x1);
    cudaGetSymbolAddress((void**)&xm16,   g_xm16);
    cudaGetSymbolAddress((void**)&h16,    g_h16);
    cudaGetSymbolAddress((void**)&wqkv16, g_wqkv16);
    cudaGetSymbolAddress((void**)&wu16,   g_wu16);
    cudaGetSymbolAddress((void**)&w116,   g_w116);
    cudaGetSymbolAddress((void**)&w216,   g_w216);

    cudaFuncSetAttribute(attn_mma, cudaFuncAttributeMaxDynamicSharedMemorySize,
                         ATTN_SMEM);
    cudaFuncSetAttribute(hgemm_mma<0, 1, __half>,
                         cudaFuncAttributeMaxDynamicSharedMemorySize, GSMEM);
    cudaFuncSetAttribute(hgemm_mma<1, 0, float>,
                         cudaFuncAttributeMaxDynamicSharedMemorySize, GSMEM);
    cudaFuncSetAttribute(hgemm_mma<2, 0, __half>,
                         cudaFuncAttributeMaxDynamicSharedMemorySize, GSMEM);

    // fused weight conversion (8M elements, one launch)
    f2h_all<<<8192, 256>>>(Wq, Wk, Wv, Wu, W1, W2);

    dim3 gQKV(3 * Dm / 128, ROWS / 128); // (24, 64) -> 1536 CTAs, 5.2 waves
    dim3 gD(Dm / 128, ROWS / 128);       // (8, 64)
    dim3 gF(FFm / 128, ROWS / 128);      // (16, 64)

    ln_kernel<<<ROWS, 256>>>(x, g1, be1, xn16);

    // fused QKV GEMM, three DENSE outputs (stride Dm each)
    hgemm_mma<0, 1, __half><<<gQKV, 256, GSMEM>>>(
        xn16, wqkv16, nullptr, nullptr, q16, k16, v16, ROWS, 3 * Dm, Dm);

    attn_mma<<<dim3(Sq / 64, Bsz * Hn), 128, ATTN_SMEM>>>(q16, k16, v16, pmask, ao16);

    hgemm_mma<1, 0, float><<<gD, 256, GSMEM>>>(
        ao16, wu16, bu, x, x1, nullptr, nullptr, ROWS, Dm, Dm);

    ln_kernel<<<ROWS, 256>>>(x1, g2, be2, xm16);

    hgemm_mma<2, 0, __half><<<gF, 256, GSMEM>>>(
        xm16, w116, b1, nullptr, h16, nullptr, nullptr, ROWS, FFm, Dm);

    hgemm_mma<1, 0, float><<<gD, 256, GSMEM>>>(
        h16, w216, b2, x1, out, nullptr, nullptr, ROWS, Dm, FFm);
}

// round 14
// speedup vs baseline: 1.6858x; 1.0239x over previous
#include <cuda_runtime.h>
#include <cuda_fp16.h>
#include <math.h>
#include <stdint.h>

#define Bsz 4
#define Sq  2048
#define Dm  1024
#define Hn  16
#define HDm 64
#define FFm 2048
#define ROWS (Bsz * Sq)   // 8192

// ---------------- scratch (no allocations allowed) ----------------
__device__ __half g_xn16[ROWS * Dm];
__device__ __half g_q16[ROWS * Dm];
__device__ __half g_k16[ROWS * Dm];
__device__ __half g_v16[ROWS * Dm];
__device__ __half g_ao16[ROWS * Dm];
__device__ float  g_x1[ROWS * Dm];
__device__ __half g_xm16[ROWS * Dm];
__device__ __half g_h16[ROWS * FFm];
__device__ __half g_wqkv16[3 * Dm * Dm];   // Wq | Wk | Wv segments (fused N=3072)
__device__ __half g_wu16[Dm * Dm];
__device__ __half g_w116[FFm * Dm];
__device__ __half g_w216[Dm * FFm];

// ---------------- PTX helpers (sm_80-portable only!) ----------------
__device__ __forceinline__ uint32_t smem_u32(const void* p) {
    uint32_t a;
    asm("{ .reg .u64 t; cvta.to.shared.u64 t, %1; cvt.u32.u64 %0, t; }"
        : "=r"(a) : "l"(p));
    return a;
}
__device__ __forceinline__ void cp16(uint32_t saddr, const void* gaddr) {
    asm volatile("cp.async.cg.shared.global [%0], [%1], 16;"
                 :: "r"(saddr), "l"(gaddr));
}
#define CP_COMMIT() asm volatile("cp.async.commit_group;" ::: "memory")
#define CP_WAIT1()  asm volatile("cp.async.wait_group 1;" ::: "memory")
#define CP_WAIT0()  asm volatile("cp.async.wait_group 0;" ::: "memory")
#define SWZ(o) ((o) ^ (((o) >> 3) & 0x70))

__device__ __forceinline__ void ldsm4(uint32_t* r, uint32_t addr) {
    asm volatile("ldmatrix.sync.aligned.m8n8.x4.shared.b16 {%0,%1,%2,%3}, [%4];"
                 : "=r"(r[0]), "=r"(r[1]), "=r"(r[2]), "=r"(r[3]) : "r"(addr));
}
__device__ __forceinline__ void ldsm4t(uint32_t* r, uint32_t addr) {
    asm volatile("ldmatrix.sync.aligned.m8n8.x4.trans.shared.b16 {%0,%1,%2,%3}, [%4];"
                 : "=r"(r[0]), "=r"(r[1]), "=r"(r[2]), "=r"(r[3]) : "r"(addr));
}
__device__ __forceinline__ void mma16816(float* c, const uint32_t* a,
                                         const uint32_t* b) {
    asm volatile("mma.sync.aligned.m16n8k16.row.col.f32.f16.f16.f32 "
                 "{%0,%1,%2,%3}, {%4,%5,%6,%7}, {%8,%9}, {%0,%1,%2,%3};"
                 : "+f"(c[0]), "+f"(c[1]), "+f"(c[2]), "+f"(c[3])
                 : "r"(a[0]), "r"(a[1]), "r"(a[2]), "r"(a[3]),
                   "r"(b[0]), "r"(b[1]));
}

// fast float 2^y (y <= 0 expected; clamped). rel err ~1e-6. Used only for alpha.
#define L2E 1.4426950408889634f
__device__ __forceinline__ float fexp2n(float y) {
    y = fmaxf(y, -125.f);
    float t = y + 12582912.f;               // 1.5 * 2^23 rounding trick
    int n = __float_as_int(t) - 0x4B400000;
    float f = y - (t - 12582912.f);         // f in [-0.5, 0.5]
    float p = 1.f + f * (0.693147182f + f * (0.240226507f + f * (0.0555041087f
              + f * (0.00961812911f + f * 0.00133335581f))));
    return __int_as_float(__float_as_int(p) + (n << 23));
}

// half2 SIMD 2^y for y in (-inf, ~0]; clamps at -14 (exp2(-14)~6e-5 ~ 0).
// 1536-offset trick; per-lane exponent injection via one 32-bit sub+shl
// (lane values <= 0x3C00, so the shift never spills across lanes).
// (named to avoid collision with cuda_fp16.hpp's h2exp2)
__device__ __forceinline__ __half2 h2exp2f_(__half2 y) {
    y = __hmax2(y, __float2half2_rn(-14.f));
    const __half2 c1536 = __float2half2_rn(1536.f);
    __half2 t = __hadd2(y, c1536);
    __half2 f = __hsub2(y, __hsub2(t, c1536));     // f in [-0.5, 0.5]
    uint32_t sb = ((*(uint32_t*)&t) - 0x65F165F1u) << 10;  // 2^n per lane
    __half2 scale = *(__half2*)&sb;
    __half2 p = __hfma2(f, __float2half2_rn(0.05550411f),
                           __float2half2_rn(0.24022651f));
    p = __hfma2(f, p, __float2half2_rn(0.69314718f));
    p = __hfma2(f, p, __float2half2_rn(1.0f));
    return __hmul2(p, scale);
}

// ---------------- LayerNorm row body (fp32 in, fp16 out) ----------------
__device__ __forceinline__ void ln_row(const float* __restrict__ x,
                                       const float* __restrict__ g,
                                       const float* __restrict__ b,
                                       __half* __restrict__ out, int row) {
    const float* xr = x + (size_t)row * Dm;
    int c = threadIdx.x * 4;
    float4 xv = *(const float4*)&xr[c];
    float s  = xv.x + xv.y + xv.z + xv.w;
    float ss = xv.x*xv.x + xv.y*xv.y + xv.z*xv.z + xv.w*xv.w;
    #pragma unroll
    for (int m = 16; m > 0; m >>= 1) {
        s  += __shfl_xor_sync(0xffffffffu, s,  m);
        ss += __shfl_xor_sync(0xffffffffu, ss, m);
    }
    __shared__ float sred[16];
    int w = threadIdx.x >> 5, lane = threadIdx.x & 31;
    if (lane == 0) { sred[w] = s; sred[w + 8] = ss; }
    __syncthreads();
    float tot = 0.f, tot2 = 0.f;
    #pragma unroll
    for (int i = 0; i < 8; i++) { tot += sred[i]; tot2 += sred[8 + i]; }
    float mean = tot * (1.0f / Dm);
    float var  = tot2 * (1.0f / Dm) - mean * mean;
    float rstd = rsqrtf(var + 1e-5f);
    float4 gv = *(const float4*)&g[c];
    float4 bv = *(const float4*)&b[c];
    float o0 = (xv.x - mean) * rstd * gv.x + bv.x;
    float o1 = (xv.y - mean) * rstd * gv.y + bv.y;
    float o2 = (xv.z - mean) * rstd * gv.z + bv.z;
    float o3 = (xv.w - mean) * rstd * gv.w + bv.w;
    __half* orow = out + (size_t)row * Dm + c;
    *(__half2*)&orow[0] = __floats2half2_rn(o0, o1);
    *(__half2*)&orow[2] = __floats2half2_rn(o2, o3);
}

__global__ void __launch_bounds__(256) ln_kernel(const float* __restrict__ x,
                                                 const float* __restrict__ g,
                                                 const float* __restrict__ b,
                                                 __half* __restrict__ out) {
    ln_row(x, g, b, out, blockIdx.x);
}

// ---------------- fused prep: LN1 rows + all weight fp32->fp16 ----------
// blocks [0, ROWS): LN1.  blocks [ROWS, ROWS+8192): weight convert.
__global__ void __launch_bounds__(256) prep_kernel(
    const float* __restrict__ x,  const float* __restrict__ g1,
    const float* __restrict__ be1,
    const float* __restrict__ Wq, const float* __restrict__ Wk,
    const float* __restrict__ Wv, const float* __restrict__ Wu,
    const float* __restrict__ W1, const float* __restrict__ W2)
{
    if (blockIdx.x < ROWS) {
        ln_row(x, g1, be1, g_xn16, blockIdx.x);
        return;
    }
    int v4 = (blockIdx.x - ROWS) * 256 + threadIdx.x;   // 0 .. 2M-1
    const float* src;
    __half* dst;
    int base;
    if      (v4 <  262144) { src = Wq; dst = g_wqkv16;               base = 0; }
    else if (v4 <  524288) { src = Wk; dst = g_wqkv16 + 1048576;     base = 262144; }
    else if (v4 <  786432) { src = Wv; dst = g_wqkv16 + 2097152;     base = 524288; }
    else if (v4 < 1048576) { src = Wu; dst = g_wu16;                 base = 786432; }
    else if (v4 < 1572864) { src = W1; dst = g_w116;                 base = 1048576; }
    else                   { src = W2; dst = g_w216;                 base = 1572864; }
    int i = (v4 - base) * 4;
    float4 v = *(const float4*)&src[i];
    *(__half2*)&dst[i]     = __floats2half2_rn(v.x, v.y);
    *(__half2*)&dst[i + 2] = __floats2half2_rn(v.z, v.w);
}

// ---------------- HMMA fp16 GEMM: C[M,N] = A[M,K] @ W[N,K]^T ----------------
// MODE 0: plain  MODE 1: +bias+residual (float out)  MODE 2: gelu(.+bias)
// QKV=1: N=3072 fused; output column block colBase>>10 selects C/C2/C3,
//        each a dense [M, Dm] buffer (keeps attention reads stride-Dm).
#define NST 3
#define STAGE_BYTES 32768
#define GSMEM (1024 + NST * STAGE_BYTES)

__device__ __forceinline__ float gelu_exact(float v) {
    return 0.5f * v * (1.0f + erff(v * 0.70710678118654752f));
}

template<int MODE, int QKV, typename TOUT>
__global__ void __launch_bounds__(256, 2)
hgemm_mma(const __half* __restrict__ A, const __half* __restrict__ W,
          const float* __restrict__ bias, const float* __restrict__ resid,
          TOUT* __restrict__ C, TOUT* __restrict__ C2, TOUT* __restrict__ C3,
          int M, int N, int K)
{
    extern __shared__ char dsm[];
    uint32_t stage0 = (smem_u32(dsm) + 1023) & ~1023u;

    int tid  = threadIdx.x;
    int wid  = tid >> 5, lane = tid & 31;
    int wm   = wid & 1;
    int wn   = wid >> 1;
    int rowBase = blockIdx.y * 128;
    int colBase = blockIdx.x * 128;
    int nchunk = K >> 6;

    TOUT* Cd = C;
    if (QKV) {
        int mi = colBase >> 10;
        Cd = (mi == 0) ? C : ((mi == 1) ? C2 : C3);
    }
    const int strideO = QKV ? Dm : N;

    float acc[4][4][4];
    #pragma unroll
    for (int i = 0; i < 4; i++)
        #pragma unroll
        for (int j = 0; j < 4; j++)
            #pragma unroll
            for (int e = 0; e < 4; e++) acc[i][j][e] = 0.f;

    auto fill = [&](int chunk, int stage) {
        uint32_t sA = stage0 + stage * STAGE_BYTES;
        uint32_t sB = sA + 16384;
        const __half* Ab = A + (size_t)rowBase * K + chunk * 64;
        const __half* Wb = W + (size_t)colBase * K + chunk * 64;
        #pragma unroll
        for (int it = 0; it < 8; it++) {
            int idx = it * 256 + tid;
            int half = idx >> 10;
            int sub  = idx & 1023;
            int r = sub >> 3, c = sub & 7;
            uint32_t off = SWZ(r * 128 + c * 16);
            if (half == 0) cp16(sA + off, Ab + (size_t)r * K + c * 8);
            else           cp16(sB + off, Wb + (size_t)r * K + c * 8);
        }
        CP_COMMIT();
    };

    fill(0, 0);
    fill(1, 1);

    int a_row_off = lane & 15;
    int a_k_off   = (lane >> 4) << 4;
    int b_row_off = (lane & 7) + ((lane >> 4) << 3);
    int b_k_off   = ((lane >> 3) & 1) << 4;

    for (int i = 0; i < nchunk; i++) {
        CP_WAIT1();
        __syncthreads();        // orders cp.async visibility AND stage reuse
        if (i + 2 < nchunk) fill(i + 2, (i + 2) % NST);

        uint32_t sA = stage0 + (i % NST) * STAGE_BYTES;
        uint32_t sB = sA + 16384;
        #pragma unroll
        for (int ks = 0; ks < 4; ks++) {
            int kb = ks * 32;
            uint32_t af[4][4], bf[2][4];
            #pragma unroll
            for (int m = 0; m < 4; m++) {
                int row = wm * 64 + m * 16 + a_row_off;
                ldsm4(af[m], sA + SWZ(row * 128 + kb + a_k_off));
            }
            #pragma unroll
            for (int j = 0; j < 2; j++) {
                int row = wn * 32 + j * 16 + b_row_off;
                ldsm4(bf[j], sB + SWZ(row * 128 + kb + b_k_off));
            }
            #pragma unroll
            for (int m = 0; m < 4; m++)
                #pragma unroll
                for (int n = 0; n < 4; n++)
                    mma16816(acc[m][n], af[m], &bf[n >> 1][(n & 1) * 2]);
        }
    }

    int r0 = rowBase + wm * 64 + (lane >> 2);
    int c0 = colBase + wn * 32 + (lane & 3) * 2;
    #pragma unroll
    for (int m = 0; m < 4; m++) {
        #pragma unroll
        for (int n = 0; n < 4; n++) {
            int col = c0 + n * 8;
            int cw  = QKV ? (col & 1023) : col;
            float2 bi = make_float2(0.f, 0.f);
            if (MODE >= 1) bi = *(const float2*)&bias[col];
            #pragma unroll
            for (int hrow = 0; hrow < 2; hrow++) {
                int row = r0 + m * 16 + hrow * 8;
                float v0 = acc[m][n][hrow * 2 + 0];
                float v1 = acc[m][n][hrow * 2 + 1];
                if (MODE >= 1) { v0 += bi.x; v1 += bi.y; }
                if (MODE == 1) {
                    float2 rr = *(const float2*)&resid[(size_t)row * N + col];
                    v0 += rr.x; v1 += rr.y;
                }
                if (MODE == 2) { v0 = gelu_exact(v0); v1 = gelu_exact(v1); }
                if (sizeof(TOUT) == 2) {
                    *(__half2*)((__half*)Cd + (size_t)row * strideO + cw) =
                        __floats2half2_rn(v0, v1);
                } else {
                    *(float2*)((float*)Cd + (size_t)row * strideO + cw) =
                        make_float2(v0, v1);
                }
            }
        }
    }
}

// ---------------- HMMA flash attention (dense q/k/v, stride Dm) ----------
// CTA: 128 threads (4 warps), 64 q-rows. K/V streamed in 64-row tiles,
// double-buffered. smem: Q 8KB | 2 x (K 8KB + V 8KB) | mask 8KB = 48KB.
// Softmax in log2 domain, half2 SIMD exp (results ARE the P fragments).
// Row sums come from an extra mma against an all-ones B fragment — the
// tensor core does the 64-col reduction AND the quad reduction for free.
#define ATTN_SMEM (8192 + 2 * 16384 + 8192)

__global__ void __launch_bounds__(128) attn_mma(
    const __half* __restrict__ q, const __half* __restrict__ k,
    const __half* __restrict__ v, const float* __restrict__ pm,
    __half* __restrict__ out)
{
    extern __shared__ char smraw[];
    uint32_t base = smem_u32(smraw);
    float* Msk = (float*)(smraw + 8192 + 32768);

    int tid = threadIdx.x, wid = tid >> 5, lane = tid & 31;
    int qtile = blockIdx.x, bh = blockIdx.y;
    int b = bh >> 4, h = bh & 15;
    int q0 = qtile * 64;

    const __half* qb = q + ((size_t)b * Sq) * Dm + h * HDm;
    const __half* kb = k + ((size_t)b * Sq) * Dm + h * HDm;
    const __half* vb = v + ((size_t)b * Sq) * Dm + h * HDm;

    // mask -> smem: additive bias pre-scaled by log2(e) (log2-domain softmax)
    {
        const float4* pmb = (const float4*)(pm + (size_t)b * Sq);
        const float MB = -10000.f * L2E;
        for (int i = tid; i < Sq / 4; i += 128) {
            float4 mv = pmb[i];
            float4 w;
            w.x = (1.f - mv.x) * MB; w.y = (1.f - mv.y) * MB;
            w.z = (1.f - mv.z) * MB; w.w = (1.f - mv.w) * MB;
            ((float4*)Msk)[i] = w;
        }
    }

    // Q tile -> smem (group 0)
    #pragma unroll
    for (int it = 0; it < 4; it++) {
        int idx = it * 128 + tid;
        int r = idx >> 3, c = idx & 7;
        cp16(base + SWZ(r * 128 + c * 16), qb + (size_t)(q0 + r) * Dm + c * 8);
    }
    CP_COMMIT();

    auto fillkv = [&](int kt, int st) {
        uint32_t sK = base + 8192 + st * 16384;
        uint32_t sV = sK + 8192;
        int k0 = kt * 64;
        #pragma unroll
        for (int it = 0; it < 8; it++) {
            int idx = it * 128 + tid;
            int hf = idx >> 9, sub = idx & 511;
            int r = sub >> 3, c = sub & 7;
            uint32_t off = SWZ(r * 128 + c * 16);
            if (hf == 0) cp16(sK + off, kb + (size_t)(k0 + r) * Dm + c * 8);
            else         cp16(sV + off, vb + (size_t)(k0 + r) * Dm + c * 8);
        }
        CP_COMMIT();
    };
    fillkv(0, 0);

    CP_WAIT1();                 // Q tile resident (kv0 may still be in flight)
    __syncthreads();

    int a_row = lane & 15, a_kb = (lane >> 4) << 4;
    int b_row = (lane & 7) + ((lane >> 4) << 3);
    int b_kb  = ((lane >> 3) & 1) << 4;
    int colb  = (lane & 3) * 2;

    uint32_t qf[4][4];
    #pragma unroll
    for (int ks = 0; ks < 4; ks++)
        ldsm4(qf[ks], base + SWZ((wid * 16 + a_row) * 128 + ks * 32 + a_kb));

    float m_[2] = {-1e30f, -1e30f}, l_[2] = {0.f, 0.f};
    float o[8][4];
    #pragma unroll
    for (int nb = 0; nb < 8; nb++)
        #pragma unroll
        for (int e = 0; e < 4; e++) o[nb][e] = 0.f;

    const float CSC = 0.125f * L2E;     // score scale folded with log2(e)
    const uint32_t ONES2[2] = {0x3C003C00u, 0x3C003C00u};  // ones B fragment

    for (int kt = 0; kt < Sq / 64; kt++) {
        int st = kt & 1;
        if (kt + 1 < Sq / 64) { fillkv(kt + 1, st ^ 1); CP_WAIT1(); }
        else                  { CP_WAIT0(); }
        __syncthreads();
        uint32_t sK = base + 8192 + st * 16384;
        uint32_t sV = sK + 8192;
        int k0 = kt * 64;

        // S = Q @ K^T
        float sc[8][4];
        #pragma unroll
        for (int nb = 0; nb < 8; nb++)
            #pragma unroll
            for (int e = 0; e < 4; e++) sc[nb][e] = 0.f;
        #pragma unroll
        for (int np = 0; np < 4; np++) {
            #pragma unroll
            for (int ks = 0; ks < 4; ks++) {
                uint32_t bf[4];
                ldsm4(bf, sK + SWZ((np * 16 + b_row) * 128 + ks * 32 + b_kb));
                mma16816(sc[2 * np],     qf[ks], &bf[0]);
                mma16816(sc[2 * np + 1], qf[ks], &bf[2]);
            }
        }

        // log2-domain scores -> half2 pairs; row max via hmax2
        __half2 ps0[8], ps1[8];
        __half2 ymax0 = __float2half2_rn(-60000.f);
        __half2 ymax1 = ymax0;
        #pragma unroll
        for (int nb = 0; nb < 8; nb++) {
            float mk0 = Msk[k0 + nb * 8 + colb];
            float mk1 = Msk[k0 + nb * 8 + colb + 1];
            ps0[nb] = __floats2half2_rn(fmaf(sc[nb][0], CSC, mk0),
                                        fmaf(sc[nb][1], CSC, mk1));
            ps1[nb] = __floats2half2_rn(fmaf(sc[nb][2], CSC, mk0),
                                        fmaf(sc[nb][3], CSC, mk1));
            ymax0 = __hmax2(ymax0, ps0[nb]);
            ymax1 = __hmax2(ymax1, ps1[nb]);
        }
        float ml0 = fmaxf(__low2float(ymax0), __high2float(ymax0));
        float ml1 = fmaxf(__low2float(ymax1), __high2float(ymax1));
        ml0 = fmaxf(ml0, __shfl_xor_sync(0xffffffffu, ml0, 1));
        ml0 = fmaxf(ml0, __shfl_xor_sync(0xffffffffu, ml0, 2));
        ml1 = fmaxf(ml1, __shfl_xor_sync(0xffffffffu, ml1, 1));
        ml1 = fmaxf(ml1, __shfl_xor_sync(0xffffffffu, ml1, 2));
        float mn0 = fmaxf(m_[0], ml0), mn1 = fmaxf(m_[1], ml1);
        float al0 = fexp2n(m_[0] - mn0);
        float al1 = fexp2n(m_[1] - mn1);
        __half2 mh0 = __float2half2_rn(mn0), mh1 = __float2half2_rn(mn1);

        // P = 2^(y - mn) in half2 (directly usable as mma A-fragments)
        #pragma unroll
        for (int nb = 0; nb < 8; nb++) {
            ps0[nb] = h2exp2f_(__hsub2(ps0[nb], mh0));
            ps1[nb] = h2exp2f_(__hsub2(ps1[nb], mh1));
        }

        // rescale O BEFORE accumulating this tile's PV
        #pragma unroll
        for (int nb = 0; nb < 8; nb++) {
            o[nb][0] *= al0; o[nb][1] *= al0;
            o[nb][2] *= al1; o[nb][3] *= al1;
        }

        // O += P @ V; row sums via ones-mma (tensor core reduces cols+quad)
        float suma[4] = {0.f, 0.f, 0.f, 0.f};
        #pragma unroll
        for (int ks = 0; ks < 4; ks++) {
            uint32_t pa[4];
            pa[0] = *(uint32_t*)&ps0[2 * ks];
            pa[1] = *(uint32_t*)&ps1[2 * ks];
            pa[2] = *(uint32_t*)&ps0[2 * ks + 1];
            pa[3] = *(uint32_t*)&ps1[2 * ks + 1];
            mma16816(suma, pa, ONES2);
            #pragma unroll
            for (int np = 0; np < 4; np++) {
                uint32_t vf[4];
                ldsm4t(vf, sV + SWZ((ks * 16 + a_row) * 128 + np * 32 + a_kb));
                mma16816(o[2 * np],     pa, &vf[0]);
                mma16816(o[2 * np + 1], pa, &vf[2]);
            }
        }
        l_[0] = l_[0] * al0 + suma[0];
        l_[1] = l_[1] * al1 + suma[2];
        m_[0] = mn0; m_[1] = mn1;
        __syncthreads();
    }

    float inv0 = 1.f / l_[0], inv1 = 1.f / l_[1];
    int r0g = q0 + wid * 16 + (lane >> 2);
    __half* ob = out + ((size_t)b * Sq) * Dm + h * HDm;
    #pragma unroll
    for (int nb = 0; nb < 8; nb++) {
        int col = nb * 8 + colb;
        *(__half2*)&ob[(size_t)r0g * Dm + col] =
            __floats2half2_rn(o[nb][0] * inv0, o[nb][1] * inv0);
        *(__half2*)&ob[(size_t)(r0g + 8) * Dm + col] =
            __floats2half2_rn(o[nb][2] * inv1, o[nb][3] * inv1);
    }
}

// ---------------- launch ----------------
extern "C" void kernel_launch(void* const* d_in, const int* in_sizes, int n_in,
                              void* d_out, int out_size) {
    const float* x     = (const float*)d_in[0];
    const float* pmask = (const float*)d_in[1];
    const float* Wq    = (const float*)d_in[2];
    const float* Wk    = (const float*)d_in[3];
    const float* Wv    = (const float*)d_in[4];
    const float* Wu    = (const float*)d_in[5];
    const float* bu    = (const float*)d_in[6];
    const float* W1    = (const float*)d_in[7];
    const float* b1    = (const float*)d_in[8];
    const float* W2    = (const float*)d_in[9];
    const float* b2    = (const float*)d_in[10];
    const float* g1    = (const float*)d_in[11];
    const float* be1   = (const float*)d_in[12];
    const float* g2    = (const float*)d_in[13];
    const float* be2   = (const float*)d_in[14];
    float* out = (float*)d_out;

    __half *xn16, *q16, *k16, *v16, *ao16, *xm16, *h16;
    __half *wqkv16, *wu16, *w116, *w216;
    float *x1;
    cudaGetSymbolAddress((void**)&xn16,   g_xn16);
    cudaGetSymbolAddress((void**)&q16,    g_q16);
    cudaGetSymbolAddress((void**)&k16,    g_k16);
    cudaGetSymbolAddress((void**)&v16,    g_v16);
    cudaGetSymbolAddress((void**)&ao16,   g_ao16);
    cudaGetSymbolAddress((void**)&x1,     g_x1);
    cudaGetSymbolAddress((void**)&xm16,   g_xm16);
    cudaGetSymbolAddress((void**)&h16,    g_h16);
    cudaGetSymbolAddress((void**)&wqkv16, g_wqkv16);
    cudaGetSymbolAddress((void**)&wu16,   g_wu16);
    cudaGetSymbolAddress((void**)&w116,   g_w116);
    cudaGetSymbolAddress((void**)&w216,   g_w216);

    cudaFuncSetAttribute(attn_mma, cudaFuncAttributeMaxDynamicSharedMemorySize,
                         ATTN_SMEM);
    cudaFuncSetAttribute(hgemm_mma<0, 1, __half>,
                         cudaFuncAttributeMaxDynamicSharedMemorySize, GSMEM);
    cudaFuncSetAttribute(hgemm_mma<1, 0, float>,
                         cudaFuncAttributeMaxDynamicSharedMemorySize, GSMEM);
    cudaFuncSetAttribute(hgemm_mma<2, 0, __half>,
                         cudaFuncAttributeMaxDynamicSharedMemorySize, GSMEM);

    // fused LN1 + weight conversion (one launch, overlapped streams)
    prep_kernel<<<ROWS + 8192, 256>>>(x, g1, be1, Wq, Wk, Wv, Wu, W1, W2);

    dim3 gQKV(3 * Dm / 128, ROWS / 128); // (24, 64) -> 1536 CTAs, 5.2 waves
    dim3 gD(Dm / 128, ROWS / 128);       // (8, 64)
    dim3 gF(FFm / 128, ROWS / 128);      // (16, 64)

    // fused QKV GEMM, three DENSE outputs (stride Dm each)
    hgemm_mma<0, 1, __half><<<gQKV, 256, GSMEM>>>(
        xn16, wqkv16, nullptr, nullptr, q16, k16, v16, ROWS, 3 * Dm, Dm);

    attn_mma<<<dim3(Sq / 64, Bsz * Hn), 128, ATTN_SMEM>>>(q16, k16, v16, pmask, ao16);

    hgemm_mma<1, 0, float><<<gD, 256, GSMEM>>>(
        ao16, wu16, bu, x, x1, nullptr, nullptr, ROWS, Dm, Dm);

    ln_kernel<<<ROWS, 256>>>(x1, g2, be2, xm16);

    hgemm_mma<2, 0, __half><<<gF, 256, GSMEM>>>(
        xm16, w116, b1, nullptr, h16, nullptr, nullptr, ROWS, FFm, Dm);

    hgemm_mma<1, 0, float><<<gD, 256, GSMEM>>>(
        h16, w216, b2, x1, out, nullptr, nullptr, ROWS, Dm, FFm);
}